// round 11
// baseline (speedup 1.0000x reference)
#include <cuda_runtime.h>
#include <math.h>

#define Bb 4
#define Nn 32
#define Mm 64
#define Kk 16
#define K1 17
#define Pp 128
#define Ww 128
#define TWd 256

typedef unsigned long long ull;

// ---------- f32x2 helpers ----------
__device__ __forceinline__ ull pack2(float a, float b) {
    ull r; asm("mov.b64 %0, {%1, %2};" : "=l"(r) : "f"(a), "f"(b)); return r;
}
__device__ __forceinline__ void unpack2(ull v, float& a, float& b) {
    asm("mov.b64 {%0, %1}, %2;" : "=f"(a), "=f"(b) : "l"(v));
}
__device__ __forceinline__ void fma2(ull& d, ull a, ull b) {
    asm("fma.rn.f32x2 %0, %1, %2, %0;" : "+l"(d) : "l"(a), "l"(b));
}
__device__ __forceinline__ ull add2(ull a, ull b) {
    ull r; asm("add.rn.f32x2 %0, %1, %2;" : "=l"(r) : "l"(a), "l"(b)); return r;
}
// exact identity tanh = 1 - 2/(exp(2x)+1); only error is __expf rounding (~2^-21)
__device__ __forceinline__ float ftanh(float x) {
    float e = __expf(2.0f * x);
    return 1.0f - __fdividef(2.0f, e + 1.0f);
}

// ------- scratch (device globals; no runtime allocation) -------
__device__ float d_A[Bb*Nn*K1*TWd];
__device__ float d_Bm[Bb*Mm*TWd];
__device__ float d_gdot[Bb*Nn*Mm];
__device__ float d_sw0T[Ww*Ww];   // [w][i]
__device__ float d_sw1T[Ww*Ww];   // [w][i]

// =====================================================================
// K_tr: transpose sw0/sw1 for coalesced column access in stages 2/4
// =====================================================================
__global__ void k_tr(const float* __restrict__ sw0, const float* __restrict__ sw1)
{
    const int idx = blockIdx.x*256 + threadIdx.x;  // 0..16383
    const int i = idx >> 7, w = idx & 127;
    d_sw0T[w*Ww + i] = sw0[idx];
    d_sw1T[w*Ww + i] = sw1[idx];
}

// =====================================================================
// K1: attention MLP + softmax + coeff + A-partial.  One block per (b,n,k1).
// =====================================================================
__global__ void __launch_bounds__(128) k1_attn(
    const float* __restrict__ phase, const float* __restrict__ posc,
    const float* __restrict__ sigma, const float* __restrict__ velc,
    const float* __restrict__ aw0, const float* __restrict__ ab0,
    const float* __restrict__ aw1, const float* __restrict__ ab1,
    const float* __restrict__ aw2, const float* __restrict__ ab2,
    const float* __restrict__ tw0, const float* __restrict__ tb0)
{
    __shared__ float s_aw0[6*64];
    __shared__ float s_ab0[64];
    __shared__ float s_aw1[64*64];
    __shared__ float s_ab1[64];
    __shared__ float s_aw2[64];
    __shared__ float red[128];

    const int bx = blockIdx.x;
    const int k1 = bx % K1;
    const int n  = (bx / K1) % Nn;
    const int b  = bx / (K1*Nn);
    const int t  = threadIdx.x;

    for (int i = t; i < 6*64; i += 128) s_aw0[i] = aw0[i];
    if (t < 64) { s_ab0[t] = ab0[t]; s_aw2[t] = aw2[t]; s_ab1[t] = ab1[t]; }
    for (int i = t; i < 64*64; i += 128) s_aw1[i] = aw1[i];
    __syncthreads();

    const float x0 = phase[(b*Nn+n)*4 + 0];
    const float x1 = phase[(b*Nn+n)*4 + 1];
    float va0, va1;
    if (k1 == 0) { va0 = phase[(b*Nn+n)*4 + 2]; va1 = phase[(b*Nn+n)*4 + 3]; }
    else         { va0 = velc[(b*Kk + (k1-1))*2 + 0]; va1 = velc[(b*Kk + (k1-1))*2 + 1]; }
    const float inv = rsqrtf(va0*va0 + va1*va1 + 1e-16f);
    const float ag0 = va0*inv, ag1 = va1*inv;

    const float rx = x0 - posc[(b*Pp + t)*2 + 0];
    const float ry = x1 - posc[(b*Pp + t)*2 + 1];
    const float rd = sqrtf(rx*rx + ry*ry + 1e-16f);
    const float pl = rx*ag0 + ry*ag1;
    const float al = pl / (rd + 1e-8f);

    float h0[64];
#pragma unroll
    for (int j = 0; j < 64; j++) {
        h0[j] = ftanh(s_ab0[j] + x0*s_aw0[0*64+j] + x1*s_aw0[1*64+j]
                              + va0*s_aw0[2*64+j] + va1*s_aw0[3*64+j]
                              + al*s_aw0[4*64+j] + pl*s_aw0[5*64+j]);
    }
    float logit = ab2[0];
#pragma unroll
    for (int g = 0; g < 4; g++) {
        ull acc[8];
#pragma unroll
        for (int p = 0; p < 8; p++) acc[p] = 0ull;
        for (int j = 0; j < 64; j++) {
            const ull hp = pack2(h0[j], h0[j]);
            const float* wrow = &s_aw1[j*64 + g*16];
            ulonglong2 wA = *reinterpret_cast<const ulonglong2*>(wrow + 0);
            ulonglong2 wB = *reinterpret_cast<const ulonglong2*>(wrow + 4);
            ulonglong2 wC = *reinterpret_cast<const ulonglong2*>(wrow + 8);
            ulonglong2 wD = *reinterpret_cast<const ulonglong2*>(wrow + 12);
            fma2(acc[0], hp, wA.x); fma2(acc[1], hp, wA.y);
            fma2(acc[2], hp, wB.x); fma2(acc[3], hp, wB.y);
            fma2(acc[4], hp, wC.x); fma2(acc[5], hp, wC.y);
            fma2(acc[6], hp, wD.x); fma2(acc[7], hp, wD.y);
        }
#pragma unroll
        for (int p = 0; p < 8; p++) {
            const int i = g*16 + p*2;
            float a0, a1; unpack2(acc[p], a0, a1);
            logit += ftanh(a0 + s_ab1[i])   * s_aw2[i]
                   + ftanh(a1 + s_ab1[i+1]) * s_aw2[i+1];
        }
    }

    float lg = (pl > 0.0f) ? logit : -1e30f;
    red[t] = lg; __syncthreads();
    for (int s = 64; s > 0; s >>= 1) { if (t < s) red[t] = fmaxf(red[t], red[t+s]); __syncthreads(); }
    const float mx = red[0]; __syncthreads();
    const float e = __expf(lg - mx);
    red[t] = e; __syncthreads();
    for (int s = 64; s > 0; s >>= 1) { if (t < s) red[t] += red[t+s]; __syncthreads(); }
    const float denom = red[0]; __syncthreads();
    const float aw = e / denom;

    const float sg0 = sigma[(b*Pp+t)*2 + 0];
    const float sg1 = sigma[(b*Pp+t)*2 + 1];
    red[t] = aw*sg0; __syncthreads();
    for (int s = 64; s > 0; s >>= 1) { if (t < s) red[t] += red[t+s]; __syncthreads(); }
    const float sum0 = red[0]; __syncthreads();
    red[t] = aw*sg1; __syncthreads();
    for (int s = 64; s > 0; s >>= 1) { if (t < s) red[t] += red[t+s]; __syncthreads(); }
    const float sum1 = red[0]; __syncthreads();

    const float c0 = __expf(-sum0);
    const float c1 = __expf(-sum1);

    for (int tt = t; tt < TWd; tt += 128) {
        float a = tb0[tt]
                + x0*tw0[0*TWd+tt] + x1*tw0[1*TWd+tt]
                + va0*tw0[2*TWd+tt] + va1*tw0[3*TWd+tt]
                + c0*tw0[8*TWd+tt] + c1*tw0[9*TWd+tt];
        d_A[bx*TWd + tt] = a;
    }
}

// =====================================================================
__global__ void k_bm(const float* __restrict__ bcoords, const float* __restrict__ tw0)
{
    const int bm = blockIdx.x;
    const int t  = threadIdx.x;
    const float xp0 = bcoords[bm*4+0], xp1 = bcoords[bm*4+1];
    const float vp0 = bcoords[bm*4+2], vp1 = bcoords[bm*4+3];
    d_Bm[bm*TWd + t] = xp0*tw0[4*TWd+t] + xp1*tw0[5*TWd+t]
                     + vp0*tw0[6*TWd+t] + vp1*tw0[7*TWd+t];
}

// =====================================================================
// K4 (256 threads): single-weight-pass layer1 via k-split across thread
// halves; layer2 j-split x2 + k-split x2; stage2 k-split x4; stage4
// w-split x2.  Low regs (~80) -> 3 blocks/SM = 6 warps/SMSP.
// =====================================================================
__global__ void __launch_bounds__(256, 3) k4_main(
    const float* __restrict__ scat, const float* __restrict__ sscat,
    const float* __restrict__ vwt,
    const float* __restrict__ tw1, const float* __restrict__ tb1,
    const float* __restrict__ tw2, const float* __restrict__ tb2,
    const float* __restrict__ sb0, const float* __restrict__ sb1,
    const float* __restrict__ out_w)
{
    __shared__ float buf[8704];      // h0/h1(17x512) -> [g(17x256)|rr or partials(17x256)]
    __shared__ ull   ws2[272];
    __shared__ float sres[256];      // resv2: 128 pairs
    __shared__ float spart[256];     // stage4 partials: 128 pairs
    __shared__ float sred[8];

    const int bx   = blockIdx.x;              // 0..2047
    const int quad = bx & 15;                 // 2 m-pairs per block
    const int n    = (bx >> 4) & 31;
    const int b    = bx >> 9;
    const int t    = threadIdx.x;             // 0..255
    const int tp   = t & 127;                 // col-pair id
    const int th2  = t >> 7;                  // half (layer1 k-split / layer2 j-split / stage4 w-split)
    const int kb1  = th2 ? 9 : 0;
    const int kc1  = th2 ? 8 : 9;
    const int kh2  = (t >> 6) & 1;            // layer2 inner k-split
    const int tc4  = t & 63;
    const int kb2  = kh2 ? 9 : 0;
    const int kc2  = kh2 ? 8 : 9;
    const int q4   = t >> 6;                  // stage2 k-quarter (0..3)
    const int kb4  = q4 ? (1 + 4*q4) : 0;     // 0,5,9,13
    const int kc4  = q4 ? 4 : 5;

    for (int i = t; i < 272; i += 256) {
        const int row = i >> 4, j = i & 15;
        float v = (row == 0) ? (1.0f - scat[(b*Nn+n)*Kk + j])
                             : (1.0f - sscat[b*256 + (row-1)*Kk + j]);
        v *= vwt[b*Kk + j];
        ws2[i] = pack2(v, v);
    }

    const float* Arow = d_A + (b*Nn + n)*K1*TWd;
    const float t1a  = tb1[tp], t1b = tb1[tp+128];
    const float tb2a = tb2[tc4], tb2b = tb2[tc4+64];
    const float sb0a = sb0[tc4], sb0b = sb0[tc4+64];
    const float sb1c = sb1[tp];
    const float owc  = out_w[tp];

    for (int mm = 0; mm < 2; mm++) {
        const int pair = quad*2 + mm;

        // ---- layer 0: h0 pairs; thread t owns column t (0..255) ----
        {
            const float* bm0 = d_Bm + (b*Mm + pair*2 + 0)*TWd;
            const float b0 = bm0[t];
            const float b1 = bm0[TWd + t];
#pragma unroll
            for (int k = 0; k < K1; k++) {
                const float A = Arow[k*TWd + t];
                *reinterpret_cast<ull*>(buf + k*512 + 2*t) =
                    pack2(ftanh(A + b0), ftanh(A + b1));
            }
        }
        __syncthreads();

        // ---- layer 1: ONE pass; k-split across halves; cols tp, tp+128 ----
        {
            ull acc0[9], acc1[9];
#pragma unroll
            for (int k = 0; k < 9; k++) { acc0[k] = 0ull; acc1[k] = 0ull; }
            const float* wb = tw1 + tp;
            float wc[8], wn[8];
#pragma unroll
            for (int jj = 0; jj < 4; jj++) { wc[jj] = wb[jj*TWd]; wc[4+jj] = wb[jj*TWd + 128]; }
#pragma unroll 1
            for (int j = 0; j < TWd; j += 4) {
                if (j + 4 < TWd) {
                    const float* wp = wb + (j+4)*TWd;
#pragma unroll
                    for (int jj = 0; jj < 4; jj++) { wn[jj] = wp[jj*TWd]; wn[4+jj] = wp[jj*TWd + 128]; }
                }
                const ull pa0 = pack2(wc[0],wc[0]), pa1 = pack2(wc[1],wc[1]),
                          pa2 = pack2(wc[2],wc[2]), pa3 = pack2(wc[3],wc[3]);
                const ull pc0 = pack2(wc[4],wc[4]), pc1 = pack2(wc[5],wc[5]),
                          pc2 = pack2(wc[6],wc[6]), pc3 = pack2(wc[7],wc[7]);
#pragma unroll
                for (int k = 0; k < 9; k++) {
                    if (k < kc1) {
                        ulonglong2 ha = *reinterpret_cast<const ulonglong2*>(buf + (kb1+k)*512 + j*2);
                        ulonglong2 hb = *reinterpret_cast<const ulonglong2*>(buf + (kb1+k)*512 + j*2 + 4);
                        fma2(acc0[k], ha.x, pa0); fma2(acc0[k], ha.y, pa1);
                        fma2(acc0[k], hb.x, pa2); fma2(acc0[k], hb.y, pa3);
                        fma2(acc1[k], ha.x, pc0); fma2(acc1[k], ha.y, pc1);
                        fma2(acc1[k], hb.x, pc2); fma2(acc1[k], hb.y, pc3);
                    }
                }
#pragma unroll
                for (int q = 0; q < 8; q++) wc[q] = wn[q];
            }
            __syncthreads();   // all h0 reads done -> overwrite with h1
#pragma unroll
            for (int k = 0; k < 9; k++) {
                if (k < kc1) {
                    float x0, x1; unpack2(acc0[k], x0, x1);
                    float y0, y1; unpack2(acc1[k], y0, y1);
                    *reinterpret_cast<ull*>(buf + (kb1+k)*512 + 2*tp) =
                        pack2(ftanh(x0+t1a), ftanh(x1+t1a));
                    *reinterpret_cast<ull*>(buf + (kb1+k)*512 + 2*(tp+128)) =
                        pack2(ftanh(y0+t1b), ftanh(y1+t1b));
                }
            }
            __syncthreads();
        }

        // ---- layer 2: j-split x2 (th2) x k-split x2 (kh2), cols tc4, tc4+64 ----
        {
            ull aA[9], aB[9];
#pragma unroll
            for (int k = 0; k < 9; k++) { aA[k] = 0ull; aB[k] = 0ull; }
            const int jb = th2 * 128;
            const float* wb = tw2 + tc4;
            float wc[8], wn[8];
#pragma unroll
            for (int jj = 0; jj < 4; jj++) { wc[jj] = wb[(jb+jj)*Ww]; wc[4+jj] = wb[(jb+jj)*Ww + 64]; }
#pragma unroll 1
            for (int j = jb; j < jb + 128; j += 4) {
                if (j + 4 < jb + 128) {
                    const float* wp = wb + (j+4)*Ww;
#pragma unroll
                    for (int jj = 0; jj < 4; jj++) { wn[jj] = wp[jj*Ww]; wn[4+jj] = wp[jj*Ww + 64]; }
                }
                const ull pA0 = pack2(wc[0],wc[0]), pA1 = pack2(wc[1],wc[1]),
                          pA2 = pack2(wc[2],wc[2]), pA3 = pack2(wc[3],wc[3]);
                const ull pB0 = pack2(wc[4],wc[4]), pB1 = pack2(wc[5],wc[5]),
                          pB2 = pack2(wc[6],wc[6]), pB3 = pack2(wc[7],wc[7]);
#pragma unroll
                for (int k = 0; k < 9; k++) {
                    if (k < kc2) {
                        ulonglong2 ha = *reinterpret_cast<const ulonglong2*>(buf + (kb2+k)*512 + j*2);
                        ulonglong2 hb = *reinterpret_cast<const ulonglong2*>(buf + (kb2+k)*512 + j*2 + 4);
                        fma2(aA[k], ha.x, pA0); fma2(aA[k], ha.y, pA1);
                        fma2(aA[k], hb.x, pA2); fma2(aA[k], hb.y, pA3);
                        fma2(aB[k], ha.x, pB0); fma2(aB[k], ha.y, pB1);
                        fma2(aB[k], hb.x, pB2); fma2(aB[k], hb.y, pB3);
                    }
                }
#pragma unroll
                for (int q = 0; q < 8; q++) wc[q] = wn[q];
            }
            __syncthreads();   // h1 fully consumed; buf free for reuse
            if (th2 == 1) {    // j-half 1 stages its partials in the rr area
#pragma unroll
                for (int k = 0; k < 9; k++) {
                    if (k < kc2) {
                        *reinterpret_cast<ull*>(buf + 4352 + (kb2+k)*256 + 2*tc4)      = aA[k];
                        *reinterpret_cast<ull*>(buf + 4352 + (kb2+k)*256 + 2*(tc4+64)) = aB[k];
                    }
                }
            }
            __syncthreads();
            if (th2 == 0) {    // combine + activation -> g
#pragma unroll
                for (int k = 0; k < 9; k++) {
                    if (k < kc2) {
                        ull sA = add2(aA[k], *reinterpret_cast<const ull*>(buf + 4352 + (kb2+k)*256 + 2*tc4));
                        ull sB = add2(aB[k], *reinterpret_cast<const ull*>(buf + 4352 + (kb2+k)*256 + 2*(tc4+64)));
                        float x0, x1; unpack2(sA, x0, x1);
                        *reinterpret_cast<ull*>(buf + (kb2+k)*256 + 2*tc4) =
                            pack2(__expf(ftanh(x0+tb2a)), __expf(ftanh(x1+tb2a)));
                        unpack2(sB, x0, x1);
                        *reinterpret_cast<ull*>(buf + (kb2+k)*256 + 2*(tc4+64)) =
                            pack2(__expf(ftanh(x0+tb2b)), __expf(ftanh(x1+tb2b)));
                    }
                }
            }
            __syncthreads();
        }

        // ---- stage 1: rr[row] = sum_j ws2[row][j]*g[1+j]; k-split across halves ----
        {
            ull g2r[Kk];
#pragma unroll
            for (int j = 0; j < Kk; j++)
                g2r[j] = *reinterpret_cast<const ull*>(buf + (1+j)*256 + 2*tp);
#pragma unroll
            for (int k = 0; k < 9; k++) {
                if (k < kc1) {
                    const int row = kb1 + k;
                    ull r = 0ull;
                    const ulonglong2* wsp = reinterpret_cast<const ulonglong2*>(ws2 + row*Kk);
#pragma unroll
                    for (int jp = 0; jp < 8; jp++) {
                        const ulonglong2 wv = wsp[jp];
                        fma2(r, g2r[2*jp],   wv.x);
                        fma2(r, g2r[2*jp+1], wv.y);
                    }
                    *reinterpret_cast<ull*>(buf + 4352 + row*256 + 2*tp) = r;
                }
            }
            __syncthreads();
        }

        // ---- stage 2: g[row][c] += tanh(sw0T[:,c]@rr[row][:] + sb0[c]); k x4, C=2 ----
        {
            ull s0[5], s1[5];
#pragma unroll
            for (int k = 0; k < 5; k++) { s0[k] = 0ull; s1[k] = 0ull; }
            const float* wb = d_sw0T + tc4;
            float wc[8], wn[8];
#pragma unroll
            for (int ww = 0; ww < 4; ww++) { wc[ww] = wb[ww*Ww]; wc[4+ww] = wb[ww*Ww + 64]; }
#pragma unroll 1
            for (int w = 0; w < Ww; w += 4) {
                if (w + 4 < Ww) {
                    const float* wp = wb + (w+4)*Ww;
#pragma unroll
                    for (int ww = 0; ww < 4; ww++) { wn[ww] = wp[ww*Ww]; wn[4+ww] = wp[ww*Ww + 64]; }
                }
                const ull p0 = pack2(wc[0],wc[0]), p1 = pack2(wc[1],wc[1]),
                          p2 = pack2(wc[2],wc[2]), p3 = pack2(wc[3],wc[3]);
                const ull p4 = pack2(wc[4],wc[4]), p5 = pack2(wc[5],wc[5]),
                          p6 = pack2(wc[6],wc[6]), p7 = pack2(wc[7],wc[7]);
#pragma unroll
                for (int k = 0; k < 5; k++) {
                    if (k < kc4) {
                        ulonglong2 ra = *reinterpret_cast<const ulonglong2*>(buf + 4352 + (kb4+k)*256 + w*2);
                        ulonglong2 rb = *reinterpret_cast<const ulonglong2*>(buf + 4352 + (kb4+k)*256 + w*2 + 4);
                        fma2(s0[k], ra.x, p0); fma2(s0[k], ra.y, p1);
                        fma2(s0[k], rb.x, p2); fma2(s0[k], rb.y, p3);
                        fma2(s1[k], ra.x, p4); fma2(s1[k], ra.y, p5);
                        fma2(s1[k], rb.x, p6); fma2(s1[k], rb.y, p7);
                    }
                }
#pragma unroll
                for (int q = 0; q < 8; q++) wc[q] = wn[q];
            }
#pragma unroll
            for (int k = 0; k < 5; k++) {
                if (k < kc4) {
                    float a0, a1; unpack2(s0[k], a0, a1);
                    ull* gp = reinterpret_cast<ull*>(buf + (kb4+k)*256 + 2*tc4);
                    float g0, g1; unpack2(*gp, g0, g1);
                    *gp = pack2(g0 + ftanh(a0+sb0a), g1 + ftanh(a1+sb0a));
                    unpack2(s1[k], a0, a1);
                    gp = reinterpret_cast<ull*>(buf + (kb4+k)*256 + 2*(tc4+64));
                    unpack2(*gp, g0, g1);
                    *gp = pack2(g0 + ftanh(a0+sb0b), g1 + ftanh(a1+sb0b));
                }
            }
            __syncthreads();
        }

        // ---- stage 3: resv2[c] = sum_k rw_v[k] * g'[1+k][c] ----
        if (t < 128) {
            ull rv = 0ull;
#pragma unroll
            for (int k = 0; k < Kk; k++)
                fma2(rv, *reinterpret_cast<const ull*>(buf + (1+k)*256 + 2*t), ws2[k]);
            *reinterpret_cast<ull*>(sres + 2*t) = rv;
        }
        __syncthreads();

        // ---- stage 4: green = g'[0] + tanh(sw1T@resv2 + sb1); w-split x2 ----
        {
            ull sa = 0ull;
            const float* wb = d_sw1T + tp;
            const int w0 = th2 * 64;
#pragma unroll 1
            for (int w = w0; w < w0 + 64; w += 4) {
                const float v0w = wb[(w+0)*Ww];
                const float v1w = wb[(w+1)*Ww];
                const float v2w = wb[(w+2)*Ww];
                const float v3w = wb[(w+3)*Ww];
                ulonglong2 ra = *reinterpret_cast<const ulonglong2*>(sres + w*2);
                ulonglong2 rb = *reinterpret_cast<const ulonglong2*>(sres + w*2 + 4);
                fma2(sa, ra.x, pack2(v0w,v0w)); fma2(sa, ra.y, pack2(v1w,v1w));
                fma2(sa, rb.x, pack2(v2w,v2w)); fma2(sa, rb.y, pack2(v3w,v3w));
            }
            if (th2 == 1) *reinterpret_cast<ull*>(spart + 2*tp) = sa;
            __syncthreads();
            if (t < 128) {
                const ull tot = add2(sa, *reinterpret_cast<const ull*>(spart + 2*t));
                float a0, a1; unpack2(tot, a0, a1);
                float v0, v1; unpack2(*reinterpret_cast<const ull*>(buf + 2*t), v0, v1);
                float p0 = (v0 + ftanh(a0+sb1c)) * owc;
                float p1 = (v1 + ftanh(a1+sb1c)) * owc;
#pragma unroll
                for (int o = 16; o > 0; o >>= 1) {
                    p0 += __shfl_down_sync(0xffffffffu, p0, o);
                    p1 += __shfl_down_sync(0xffffffffu, p1, o);
                }
                if ((t & 31) == 0) { sred[(t>>5)*2] = p0; sred[(t>>5)*2+1] = p1; }
            }
            __syncthreads();
            if (t == 0) {
                d_gdot[(b*Nn+n)*Mm + pair*2 + 0] = sred[0]+sred[2]+sred[4]+sred[6];
                d_gdot[(b*Nn+n)*Mm + pair*2 + 1] = sred[1]+sred[3]+sred[5]+sred[7];
            }
            __syncthreads();
        }
    }
}

// =====================================================================
__global__ void k6_final(const float* __restrict__ boundary,
                         const float* __restrict__ bweights,
                         float* __restrict__ out)
{
    __shared__ float s2[2];
    const int bn = blockIdx.x;
    const int b  = bn >> 5;
    const int t  = threadIdx.x;
    float v = d_gdot[bn*Mm + t] * boundary[b*Mm + t] * bweights[b*Mm + t];
#pragma unroll
    for (int o = 16; o > 0; o >>= 1) v += __shfl_down_sync(0xffffffffu, v, o);
    if ((t & 31) == 0) s2[t >> 5] = v;
    __syncthreads();
    if (t == 0) out[bn] = s2[0] + s2[1];
}

// =====================================================================
extern "C" void kernel_launch(void* const* d_in, const int* in_sizes, int n_in,
                              void* d_out, int out_size)
{
    const float* phase    = (const float*)d_in[0];
    const float* bcoords  = (const float*)d_in[1];
    const float* boundary = (const float*)d_in[2];
    const float* bweights = (const float*)d_in[3];
    const float* posc     = (const float*)d_in[4];
    const float* sigma    = (const float*)d_in[5];
    const float* velc     = (const float*)d_in[6];
    const float* vwt      = (const float*)d_in[7];
    const float* scat     = (const float*)d_in[8];
    const float* sscat    = (const float*)d_in[9];
    const float* aw0 = (const float*)d_in[10];
    const float* ab0 = (const float*)d_in[11];
    const float* aw1 = (const float*)d_in[12];
    const float* ab1 = (const float*)d_in[13];
    const float* aw2 = (const float*)d_in[14];
    const float* ab2 = (const float*)d_in[15];
    const float* tw0 = (const float*)d_in[16];
    const float* tb0 = (const float*)d_in[17];
    const float* tw1 = (const float*)d_in[18];
    const float* tb1 = (const float*)d_in[19];
    const float* tw2 = (const float*)d_in[20];
    const float* tb2 = (const float*)d_in[21];
    const float* sw0 = (const float*)d_in[22];
    const float* sb0 = (const float*)d_in[23];
    const float* sw1 = (const float*)d_in[24];
    const float* sb1 = (const float*)d_in[25];
    const float* ow  = (const float*)d_in[26];
    float* out = (float*)d_out;

    k_tr<<<64, 256>>>(sw0, sw1);
    k1_attn<<<Bb*Nn*K1, 128>>>(phase, posc, sigma, velc,
                               aw0, ab0, aw1, ab1, aw2, ab2, tw0, tb0);
    k_bm<<<Bb*Mm, TWd>>>(bcoords, tw0);
    k4_main<<<Bb*Nn*(Mm/4), 256>>>(
        scat, sscat, vwt, tw1, tb1, tw2, tb2, sb0, sb1, ow);
    k6_final<<<Bb*Nn, 64>>>(boundary, bweights, out);
}

// round 13
// speedup vs baseline: 1.2328x; 1.2328x over previous
#include <cuda_runtime.h>
#include <cuda_bf16.h>
#include <math.h>
#include <cstdint>

#define Bb 4
#define Nn 32
#define Mm 64
#define Kk 16
#define K1 17
#define Pp 128
#define Ww 128
#define TWd 256
#define NROWS (Bb*Nn*Mm*K1)      /* 139264 */
#define NTILES (NROWS/128)       /* 1088 */

typedef unsigned long long ull;

// ---------- f32x2 helpers ----------
__device__ __forceinline__ ull pack2(float a, float b) {
    ull r; asm("mov.b64 %0, {%1, %2};" : "=l"(r) : "f"(a), "f"(b)); return r;
}
__device__ __forceinline__ void unpack2(ull v, float& a, float& b) {
    asm("mov.b64 {%0, %1}, %2;" : "=f"(a), "=f"(b) : "l"(v));
}
__device__ __forceinline__ void fma2(ull& d, ull a, ull b) {
    asm("fma.rn.f32x2 %0, %1, %2, %0;" : "+l"(d) : "l"(a), "l"(b));
}
__device__ __forceinline__ ull add2(ull a, ull b) {
    ull r; asm("add.rn.f32x2 %0, %1, %2;" : "=l"(r) : "l"(a), "l"(b)); return r;
}
__device__ __forceinline__ float ftanh(float x) {
    float e = __expf(2.0f * x);
    return 1.0f - __fdividef(2.0f, e + 1.0f);
}
// bf16 split helpers
__device__ __forceinline__ unsigned short bfh(float x) {
    __nv_bfloat16 h = __float2bfloat16(x);
    return *reinterpret_cast<unsigned short*>(&h);
}
__device__ __forceinline__ unsigned short bfl(float x) {
    __nv_bfloat16 h = __float2bfloat16(x);
    float r = x - __bfloat162float(h);
    __nv_bfloat16 l = __float2bfloat16(r);
    return *reinterpret_cast<unsigned short*>(&l);
}
__device__ __forceinline__ unsigned packhi2(float a, float b) {
    return (unsigned)bfh(a) | ((unsigned)bfh(b) << 16);
}
__device__ __forceinline__ unsigned packlo2(float a, float b) {
    return (unsigned)bfl(a) | ((unsigned)bfl(b) << 16);
}
__device__ __forceinline__ uint32_t smem_to_u32(const void* p) {
    uint32_t a;
    asm("{ .reg .u64 tmp; cvta.to.shared.u64 tmp, %1; cvt.u32.u64 %0, tmp; }" : "=r"(a) : "l"(p));
    return a;
}
__device__ __forceinline__ void ldm_x4(uint32_t& r0, uint32_t& r1, uint32_t& r2, uint32_t& r3, uint32_t addr) {
    asm volatile("ldmatrix.sync.aligned.m8n8.x4.shared.b16 {%0,%1,%2,%3}, [%4];"
                 : "=r"(r0), "=r"(r1), "=r"(r2), "=r"(r3) : "r"(addr));
}
__device__ __forceinline__ void mma16816(float* c, const uint32_t* a, uint32_t b0, uint32_t b1) {
    asm volatile("mma.sync.aligned.m16n8k16.row.col.f32.bf16.bf16.f32 "
                 "{%0,%1,%2,%3}, {%4,%5,%6,%7}, {%8,%9}, {%0,%1,%2,%3};"
                 : "+f"(c[0]), "+f"(c[1]), "+f"(c[2]), "+f"(c[3])
                 : "r"(a[0]), "r"(a[1]), "r"(a[2]), "r"(a[3]), "r"(b0), "r"(b1));
}

// ------- scratch (device globals; no runtime allocation) -------
__device__ float d_A[Bb*Nn*K1*TWd];
__device__ float d_Bm[Bb*Mm*TWd];
__device__ float d_gdot[Bb*Nn*Mm];
__device__ float d_sw0T[Ww*Ww];             // [w][i]
__device__ float d_sw1T[Ww*Ww];             // [w][i]
__device__ unsigned d_W1hT[256*128];        // [n][kpair] bf16x2 (hi)
__device__ unsigned d_W1lT[256*128];        // (lo)
__device__ unsigned d_W2hT[128*128];
__device__ unsigned d_W2lT[128*128];
__device__ unsigned d_H0h[NROWS*128];       // [row][kpair] bf16x2 hi
__device__ unsigned d_H0l[NROWS*128];
__device__ unsigned d_H1h[NROWS*128];
__device__ unsigned d_H1l[NROWS*128];
__device__ float    d_g [NROWS*128];

// =====================================================================
// K_prep: split-transposed weights + sw transposes
// =====================================================================
__global__ void k_prep(const float* __restrict__ tw1, const float* __restrict__ tw2,
                       const float* __restrict__ sw0, const float* __restrict__ sw1)
{
    const int idx = blockIdx.x*256 + threadIdx.x;   // 0..32767
    {
        const int n = idx >> 7, kp = idx & 127;
        const float w0 = tw1[(2*kp)*256 + n];
        const float w1 = tw1[(2*kp+1)*256 + n];
        d_W1hT[n*128 + kp] = packhi2(w0, w1);
        d_W1lT[n*128 + kp] = packlo2(w0, w1);
    }
    if (idx < 16384) {
        const int n = idx >> 7, kp = idx & 127;
        const float w0 = tw2[(2*kp)*128 + n];
        const float w1 = tw2[(2*kp+1)*128 + n];
        d_W2hT[n*128 + kp] = packhi2(w0, w1);
        d_W2lT[n*128 + kp] = packlo2(w0, w1);
        const int i = idx >> 7, w = idx & 127;
        d_sw0T[w*Ww + i] = sw0[idx];
        d_sw1T[w*Ww + i] = sw1[idx];
    }
}

// =====================================================================
// K1: attention MLP + softmax + coeff + A-partial.  One block per (b,n,k1).
// =====================================================================
__global__ void __launch_bounds__(128) k1_attn(
    const float* __restrict__ phase, const float* __restrict__ posc,
    const float* __restrict__ sigma, const float* __restrict__ velc,
    const float* __restrict__ aw0, const float* __restrict__ ab0,
    const float* __restrict__ aw1, const float* __restrict__ ab1,
    const float* __restrict__ aw2, const float* __restrict__ ab2,
    const float* __restrict__ tw0, const float* __restrict__ tb0)
{
    __shared__ float s_aw0[6*64];
    __shared__ float s_ab0[64];
    __shared__ float s_aw1[64*64];
    __shared__ float s_ab1[64];
    __shared__ float s_aw2[64];
    __shared__ float red[128];

    const int bx = blockIdx.x;
    const int k1 = bx % K1;
    const int n  = (bx / K1) % Nn;
    const int b  = bx / (K1*Nn);
    const int t  = threadIdx.x;

    for (int i = t; i < 6*64; i += 128) s_aw0[i] = aw0[i];
    if (t < 64) { s_ab0[t] = ab0[t]; s_aw2[t] = aw2[t]; s_ab1[t] = ab1[t]; }
    for (int i = t; i < 64*64; i += 128) s_aw1[i] = aw1[i];
    __syncthreads();

    const float x0 = phase[(b*Nn+n)*4 + 0];
    const float x1 = phase[(b*Nn+n)*4 + 1];
    float va0, va1;
    if (k1 == 0) { va0 = phase[(b*Nn+n)*4 + 2]; va1 = phase[(b*Nn+n)*4 + 3]; }
    else         { va0 = velc[(b*Kk + (k1-1))*2 + 0]; va1 = velc[(b*Kk + (k1-1))*2 + 1]; }
    const float inv = rsqrtf(va0*va0 + va1*va1 + 1e-16f);
    const float ag0 = va0*inv, ag1 = va1*inv;

    const float rx = x0 - posc[(b*Pp + t)*2 + 0];
    const float ry = x1 - posc[(b*Pp + t)*2 + 1];
    const float rd = sqrtf(rx*rx + ry*ry + 1e-16f);
    const float pl = rx*ag0 + ry*ag1;
    const float al = pl / (rd + 1e-8f);

    float h0[64];
#pragma unroll
    for (int j = 0; j < 64; j++) {
        h0[j] = ftanh(s_ab0[j] + x0*s_aw0[0*64+j] + x1*s_aw0[1*64+j]
                              + va0*s_aw0[2*64+j] + va1*s_aw0[3*64+j]
                              + al*s_aw0[4*64+j] + pl*s_aw0[5*64+j]);
    }
    float logit = ab2[0];
#pragma unroll
    for (int g = 0; g < 4; g++) {
        ull acc[8];
#pragma unroll
        for (int p = 0; p < 8; p++) acc[p] = 0ull;
        for (int j = 0; j < 64; j++) {
            const ull hp = pack2(h0[j], h0[j]);
            const float* wrow = &s_aw1[j*64 + g*16];
            ulonglong2 wA = *reinterpret_cast<const ulonglong2*>(wrow + 0);
            ulonglong2 wB = *reinterpret_cast<const ulonglong2*>(wrow + 4);
            ulonglong2 wC = *reinterpret_cast<const ulonglong2*>(wrow + 8);
            ulonglong2 wD = *reinterpret_cast<const ulonglong2*>(wrow + 12);
            fma2(acc[0], hp, wA.x); fma2(acc[1], hp, wA.y);
            fma2(acc[2], hp, wB.x); fma2(acc[3], hp, wB.y);
            fma2(acc[4], hp, wC.x); fma2(acc[5], hp, wC.y);
            fma2(acc[6], hp, wD.x); fma2(acc[7], hp, wD.y);
        }
#pragma unroll
        for (int p = 0; p < 8; p++) {
            const int i = g*16 + p*2;
            float a0, a1; unpack2(acc[p], a0, a1);
            logit += ftanh(a0 + s_ab1[i])   * s_aw2[i]
                   + ftanh(a1 + s_ab1[i+1]) * s_aw2[i+1];
        }
    }

    float lg = (pl > 0.0f) ? logit : -1e30f;
    red[t] = lg; __syncthreads();
    for (int s = 64; s > 0; s >>= 1) { if (t < s) red[t] = fmaxf(red[t], red[t+s]); __syncthreads(); }
    const float mx = red[0]; __syncthreads();
    const float e = __expf(lg - mx);
    red[t] = e; __syncthreads();
    for (int s = 64; s > 0; s >>= 1) { if (t < s) red[t] += red[t+s]; __syncthreads(); }
    const float denom = red[0]; __syncthreads();
    const float aw = e / denom;

    const float sg0 = sigma[(b*Pp+t)*2 + 0];
    const float sg1 = sigma[(b*Pp+t)*2 + 1];
    red[t] = aw*sg0; __syncthreads();
    for (int s = 64; s > 0; s >>= 1) { if (t < s) red[t] += red[t+s]; __syncthreads(); }
    const float sum0 = red[0]; __syncthreads();
    red[t] = aw*sg1; __syncthreads();
    for (int s = 64; s > 0; s >>= 1) { if (t < s) red[t] += red[t+s]; __syncthreads(); }
    const float sum1 = red[0]; __syncthreads();

    const float c0 = __expf(-sum0);
    const float c1 = __expf(-sum1);

    for (int tt = t; tt < TWd; tt += 128) {
        float a = tb0[tt]
                + x0*tw0[0*TWd+tt] + x1*tw0[1*TWd+tt]
                + va0*tw0[2*TWd+tt] + va1*tw0[3*TWd+tt]
                + c0*tw0[8*TWd+tt] + c1*tw0[9*TWd+tt];
        d_A[bx*TWd + tt] = a;
    }
}

// =====================================================================
__global__ void k_bm(const float* __restrict__ bcoords, const float* __restrict__ tw0)
{
    const int bm = blockIdx.x;
    const int t  = threadIdx.x;
    const float xp0 = bcoords[bm*4+0], xp1 = bcoords[bm*4+1];
    const float vp0 = bcoords[bm*4+2], vp1 = bcoords[bm*4+3];
    d_Bm[bm*TWd + t] = xp0*tw0[4*TWd+t] + xp1*tw0[5*TWd+t]
                     + vp0*tw0[6*TWd+t] + vp1*tw0[7*TWd+t];
}

// =====================================================================
// K_h0: H0 = tanh(A + Bm) as bf16-split pair arrays.  Block per (b,n,m).
// =====================================================================
__global__ void __launch_bounds__(128) k_h0()
{
    const int bnm = blockIdx.x;            // 0..8191
    const int m   = bnm & 63;
    const int bn  = bnm >> 6;              // b*32+n
    const int t   = threadIdx.x;           // pair index 0..127
    const float* Arow = d_A + bn*K1*TWd;
    const float* Bm   = d_Bm + ((bn >> 5)*Mm + m)*TWd;
    const float bm0 = Bm[2*t], bm1 = Bm[2*t+1];
#pragma unroll
    for (int k = 0; k < K1; k++) {
        const float v0 = ftanh(Arow[k*TWd + 2*t]     + bm0);
        const float v1 = ftanh(Arow[k*TWd + 2*t + 1] + bm1);
        const int o = (bnm*K1 + k)*128 + t;
        d_H0h[o] = packhi2(v0, v1);
        d_H0l[o] = packlo2(v0, v1);
    }
}

// =====================================================================
// K_g1: H1 = tanh(H0 @ tw1 + tb1) via mma.sync bf16-split.
// Block: 128 rows, 256 threads (8 warps in 2x4).  2 N-passes of 128.
// =====================================================================
__global__ void __launch_bounds__(256, 2) k_g1(const float* __restrict__ tb1)
{
    __shared__ unsigned A_s[128*12];       // [row][12] (8 used + 4 pad) bf16x2
    __shared__ unsigned B_s[128*12];       // [n][12]

    const int t   = threadIdx.x;
    const int lid = t & 31, wid = t >> 5;
    const int wm  = wid >> 2, wn = wid & 3;
    const int row0 = blockIdx.x * 128;
    const int lr = lid >> 2, lc = lid & 3;

    const uint32_t a_base = smem_to_u32(A_s);
    const uint32_t b_base = smem_to_u32(B_s);
    // per-lane ldmatrix addresses (bytes); 24 bf16 = 48B row stride
    const int arow  = wm*64 + (lid & 7) + ((lid >> 3) & 1)*8;
    const uint32_t a_addr = a_base + (uint32_t)(arow*48 + ((lid >> 4)*8)*2);
    const int brow  = wn*32 + ((lid >> 4)*8) + (lid & 7);
    const uint32_t b_addr = b_base + (uint32_t)(brow*48 + (((lid >> 3) & 1)*8)*2);

    for (int pass = 0; pass < 2; pass++) {
        float acc[4][4][4];
#pragma unroll
        for (int mi = 0; mi < 4; mi++)
#pragma unroll
            for (int ni = 0; ni < 4; ni++)
#pragma unroll
                for (int e = 0; e < 4; e++) acc[mi][ni][e] = 0.0f;

#pragma unroll 1
        for (int term = 0; term < 3; term++) {
            const unsigned* Asrc = (term < 2) ? d_H0h : d_H0l;
            const unsigned* Bsrc = (term == 1) ? d_W1lT : d_W1hT;
#pragma unroll 1
            for (int kc = 0; kc < 16; kc++) {
                __syncthreads();
#pragma unroll
                for (int i = 0; i < 4; i++) {
                    const int idx = t + i*256;      // 0..1023
                    const int r = idx >> 3, j = idx & 7;
                    A_s[r*12 + j] = Asrc[(row0 + r)*128 + kc*8 + j];
                    B_s[r*12 + j] = Bsrc[(pass*128 + r)*128 + kc*8 + j];
                }
                __syncthreads();
                uint32_t a[4][4];
#pragma unroll
                for (int mi = 0; mi < 4; mi++)
                    ldm_x4(a[mi][0], a[mi][1], a[mi][2], a[mi][3], a_addr + (uint32_t)(mi*16*48));
                uint32_t bf[2][4];
#pragma unroll
                for (int h = 0; h < 2; h++)
                    ldm_x4(bf[h][0], bf[h][1], bf[h][2], bf[h][3], b_addr + (uint32_t)(h*16*48));
#pragma unroll
                for (int mi = 0; mi < 4; mi++) {
#pragma unroll
                    for (int ni = 0; ni < 4; ni++) {
                        const int h = ni >> 1, p = ni & 1;
                        mma16816(acc[mi][ni], a[mi], bf[h][p*2], bf[h][p*2+1]);
                    }
                }
            }
        }

        // epilogue: tanh + bf16-split pack
#pragma unroll
        for (int mi = 0; mi < 4; mi++) {
#pragma unroll
            for (int ni = 0; ni < 4; ni++) {
                const int r0 = row0 + wm*64 + mi*16 + lr;
                const int colg = pass*128 + wn*32 + ni*8 + 2*lc;
                const float bb0 = __ldg(&tb1[colg]);
                const float bb1 = __ldg(&tb1[colg+1]);
                const float t0 = ftanh(acc[mi][ni][0] + bb0);
                const float t1 = ftanh(acc[mi][ni][1] + bb1);
                const float t2 = ftanh(acc[mi][ni][2] + bb0);
                const float t3 = ftanh(acc[mi][ni][3] + bb1);
                const int cp = colg >> 1;
                d_H1h[r0*128 + cp]     = packhi2(t0, t1);
                d_H1l[r0*128 + cp]     = packlo2(t0, t1);
                d_H1h[(r0+8)*128 + cp] = packhi2(t2, t3);
                d_H1l[(r0+8)*128 + cp] = packlo2(t2, t3);
            }
        }
    }
}

// =====================================================================
// K_g2: g = exp(tanh(H1 @ tw2 + tb2)) via mma.sync bf16-split.  N=128.
// =====================================================================
__global__ void __launch_bounds__(256, 2) k_g2(const float* __restrict__ tb2)
{
    __shared__ unsigned A_s[128*12];
    __shared__ unsigned B_s[128*12];

    const int t   = threadIdx.x;
    const int lid = t & 31, wid = t >> 5;
    const int wm  = wid >> 2, wn = wid & 3;
    const int row0 = blockIdx.x * 128;
    const int lr = lid >> 2, lc = lid & 3;

    const uint32_t a_base = smem_to_u32(A_s);
    const uint32_t b_base = smem_to_u32(B_s);
    const int arow  = wm*64 + (lid & 7) + ((lid >> 3) & 1)*8;
    const uint32_t a_addr = a_base + (uint32_t)(arow*48 + ((lid >> 4)*8)*2);
    const int brow  = wn*32 + ((lid >> 4)*8) + (lid & 7);
    const uint32_t b_addr = b_base + (uint32_t)(brow*48 + (((lid >> 3) & 1)*8)*2);

    float acc[4][4][4];
#pragma unroll
    for (int mi = 0; mi < 4; mi++)
#pragma unroll
        for (int ni = 0; ni < 4; ni++)
#pragma unroll
            for (int e = 0; e < 4; e++) acc[mi][ni][e] = 0.0f;

#pragma unroll 1
    for (int term = 0; term < 3; term++) {
        const unsigned* Asrc = (term < 2) ? d_H1h : d_H1l;
        const unsigned* Bsrc = (term == 1) ? d_W2lT : d_W2hT;
#pragma unroll 1
        for (int kc = 0; kc < 16; kc++) {
            __syncthreads();
#pragma unroll
            for (int i = 0; i < 4; i++) {
                const int idx = t + i*256;
                const int r = idx >> 3, j = idx & 7;
                A_s[r*12 + j] = Asrc[(row0 + r)*128 + kc*8 + j];
                B_s[r*12 + j] = Bsrc[r*128 + kc*8 + j];
            }
            __syncthreads();
            uint32_t a[4][4];
#pragma unroll
            for (int mi = 0; mi < 4; mi++)
                ldm_x4(a[mi][0], a[mi][1], a[mi][2], a[mi][3], a_addr + (uint32_t)(mi*16*48));
            uint32_t bf[2][4];
#pragma unroll
            for (int h = 0; h < 2; h++)
                ldm_x4(bf[h][0], bf[h][1], bf[h][2], bf[h][3], b_addr + (uint32_t)(h*16*48));
#pragma unroll
            for (int mi = 0; mi < 4; mi++) {
#pragma unroll
                for (int ni = 0; ni < 4; ni++) {
                    const int h = ni >> 1, p = ni & 1;
                    mma16816(acc[mi][ni], a[mi], bf[h][p*2], bf[h][p*2+1]);
                }
            }
        }
    }

#pragma unroll
    for (int mi = 0; mi < 4; mi++) {
#pragma unroll
        for (int ni = 0; ni < 4; ni++) {
            const int r0 = row0 + wm*64 + mi*16 + lr;
            const int colg = wn*32 + ni*8 + 2*lc;
            const float bb0 = __ldg(&tb2[colg]);
            const float bb1 = __ldg(&tb2[colg+1]);
            float2 v0, v1;
            v0.x = __expf(ftanh(acc[mi][ni][0] + bb0));
            v0.y = __expf(ftanh(acc[mi][ni][1] + bb1));
            v1.x = __expf(ftanh(acc[mi][ni][2] + bb0));
            v1.y = __expf(ftanh(acc[mi][ni][3] + bb1));
            *reinterpret_cast<float2*>(&d_g[r0*128 + colg])     = v0;
            *reinterpret_cast<float2*>(&d_g[(r0+8)*128 + colg]) = v1;
        }
    }
}

// =====================================================================
// K5: scattering chain on g (f32x2 over the m-pair), per (b,n,m-pair).
// =====================================================================
__global__ void __launch_bounds__(128) k5_scat(
    const float* __restrict__ scat, const float* __restrict__ sscat,
    const float* __restrict__ vwt,
    const float* __restrict__ sb0, const float* __restrict__ sb1,
    const float* __restrict__ out_w)
{
    __shared__ float buf[8704];      // g(17x256 pairs) | rr(17x256) at +4352
    __shared__ ull   ws2[272];
    __shared__ float sres[256];
    __shared__ float sred[8];

    const int bx   = blockIdx.x;              // 0..4095
    const int pair = bx & 31;
    const int n    = (bx >> 5) & 31;
    const int b    = bx >> 10;
    const int t    = threadIdx.x;
    const int th   = t >> 6;
    const int tc   = t & 63;
    const int kbs  = th ? 9 : 0;
    const int kcs  = th ? 8 : 9;

    for (int i = t; i < 272; i += 128) {
        const int row = i >> 4, j = i & 15;
        float v = (row == 0) ? (1.0f - scat[(b*Nn+n)*Kk + j])
                             : (1.0f - sscat[b*256 + (row-1)*Kk + j]);
        v *= vwt[b*Kk + j];
        ws2[i] = pack2(v, v);
    }

    const int bnm0 = ((b*Nn + n)*Mm + pair*2);
#pragma unroll
    for (int k = 0; k < K1; k++) {
        const float g0 = d_g[(bnm0*K1 + k)*128 + t];
        const float g1 = d_g[((bnm0+1)*K1 + k)*128 + t];
        *reinterpret_cast<ull*>(buf + k*256 + 2*t) = pack2(g0, g1);
    }
    __syncthreads();

    const float sb0a = sb0[tc], sb0b = sb0[tc+64];
    const float sb1c = sb1[t];
    const float owc  = out_w[t];

    // ---- stage 1: rr[k] = sum_j ws2[k][j]*g[1+j] ----
    {
        ull g2r[Kk];
#pragma unroll
        for (int j = 0; j < Kk; j++)
            g2r[j] = *reinterpret_cast<const ull*>(buf + (1+j)*256 + 2*t);
#pragma unroll
        for (int k = 0; k < K1; k++) {
            ull r = 0ull;
            const ulonglong2* wsp = reinterpret_cast<const ulonglong2*>(ws2 + k*Kk);
#pragma unroll
            for (int jp = 0; jp < 8; jp++) {
                const ulonglong2 wv = wsp[jp];
                fma2(r, g2r[2*jp],   wv.x);
                fma2(r, g2r[2*jp+1], wv.y);
            }
            *reinterpret_cast<ull*>(buf + 4352 + k*256 + 2*t) = r;
        }
        __syncthreads();
    }

    // ---- stage 2: g[k][c] += tanh(sw0T[:,c]@rr[k][:] + sb0[c]); k-split, 2 cols ----
    {
        ull sA[9], sB[9];
#pragma unroll
        for (int k = 0; k < 9; k++) { sA[k] = 0ull; sB[k] = 0ull; }
        const float* wb = d_sw0T + tc;
        float wcA[4], wcB[4], wnA[4], wnB[4];
#pragma unroll
        for (int ww = 0; ww < 4; ww++) { wcA[ww] = wb[ww*Ww]; wcB[ww] = wb[ww*Ww + 64]; }
#pragma unroll 1
        for (int w = 0; w < Ww; w += 4) {
            if (w + 4 < Ww) {
                const float* wp = wb + (w+4)*Ww;
#pragma unroll
                for (int ww = 0; ww < 4; ww++) { wnA[ww] = wp[ww*Ww]; wnB[ww] = wp[ww*Ww + 64]; }
            }
            const ull pA0 = pack2(wcA[0],wcA[0]), pA1 = pack2(wcA[1],wcA[1]),
                      pA2 = pack2(wcA[2],wcA[2]), pA3 = pack2(wcA[3],wcA[3]);
            const ull pB0 = pack2(wcB[0],wcB[0]), pB1 = pack2(wcB[1],wcB[1]),
                      pB2 = pack2(wcB[2],wcB[2]), pB3 = pack2(wcB[3],wcB[3]);
#pragma unroll
            for (int k = 0; k < 9; k++) {
                if (k < kcs) {
                    ulonglong2 ra = *reinterpret_cast<const ulonglong2*>(buf + 4352 + (kbs+k)*256 + w*2);
                    ulonglong2 rb = *reinterpret_cast<const ulonglong2*>(buf + 4352 + (kbs+k)*256 + w*2 + 4);
                    fma2(sA[k], ra.x, pA0); fma2(sA[k], ra.y, pA1);
                    fma2(sA[k], rb.x, pA2); fma2(sA[k], rb.y, pA3);
                    fma2(sB[k], ra.x, pB0); fma2(sB[k], ra.y, pB1);
                    fma2(sB[k], rb.x, pB2); fma2(sB[k], rb.y, pB3);
                }
            }
#pragma unroll
            for (int q = 0; q < 4; q++) { wcA[q] = wnA[q]; wcB[q] = wnB[q]; }
        }
#pragma unroll
        for (int k = 0; k < 9; k++) {
            if (k < kcs) {
                float a0, a1; unpack2(sA[k], a0, a1);
                ull* gp = reinterpret_cast<ull*>(buf + (kbs+k)*256 + 2*tc);
                float g0, g1; unpack2(*gp, g0, g1);
                *gp = pack2(g0 + ftanh(a0+sb0a), g1 + ftanh(a1+sb0a));
                unpack2(sB[k], a0, a1);
                gp = reinterpret_cast<ull*>(buf + (kbs+k)*256 + 2*(tc+64));
                unpack2(*gp, g0, g1);
                *gp = pack2(g0 + ftanh(a0+sb0b), g1 + ftanh(a1+sb0b));
            }
        }
        __syncthreads();
    }

    // ---- stage 3 ----
    {
        ull rv = 0ull;
#pragma unroll
        for (int k = 0; k < Kk; k++)
            fma2(rv, *reinterpret_cast<const ull*>(buf + (1+k)*256 + 2*t), ws2[k]);
        *reinterpret_cast<ull*>(sres + 2*t) = rv;
    }
    __syncthreads();

    // ---- stage 4 ----
    {
        ull sa = 0ull, sb = 0ull;
        const float* wb = d_sw1T + t;
#pragma unroll 1
        for (int w = 0; w < Ww; w += 4) {
            const float v0w = wb[(w+0)*Ww];
            const float v1w = wb[(w+1)*Ww];
            const float v2w = wb[(w+2)*Ww];
            const float v3w = wb[(w+3)*Ww];
            ulonglong2 ra = *reinterpret_cast<const ulonglong2*>(sres + w*2);
            ulonglong2 rb = *reinterpret_cast<const ulonglong2*>(sres + w*2 + 4);
            fma2(sa, ra.x, pack2(v0w,v0w)); fma2(sb, ra.y, pack2(v1w,v1w));
            fma2(sa, rb.x, pack2(v2w,v2w)); fma2(sb, rb.y, pack2(v3w,v3w));
        }
        const ull tot = add2(sa, sb);
        float a0, a1; unpack2(tot, a0, a1);
        float v0, v1; unpack2(*reinterpret_cast<const ull*>(buf + 2*t), v0, v1);
        float p0 = (v0 + ftanh(a0+sb1c)) * owc;
        float p1 = (v1 + ftanh(a1+sb1c)) * owc;
#pragma unroll
        for (int o = 16; o > 0; o >>= 1) {
            p0 += __shfl_down_sync(0xffffffffu, p0, o);
            p1 += __shfl_down_sync(0xffffffffu, p1, o);
        }
        if ((t & 31) == 0) { sred[(t>>5)*2] = p0; sred[(t>>5)*2+1] = p1; }
        __syncthreads();
        if (t == 0) {
            d_gdot[(b*Nn+n)*Mm + pair*2 + 0] = sred[0]+sred[2]+sred[4]+sred[6];
            d_gdot[(b*Nn+n)*Mm + pair*2 + 1] = sred[1]+sred[3]+sred[5]+sred[7];
        }
    }
}

// =====================================================================
__global__ void k6_final(const float* __restrict__ boundary,
                         const float* __restrict__ bweights,
                         float* __restrict__ out)
{
    __shared__ float s2[2];
    const int bn = blockIdx.x;
    const int b  = bn >> 5;
    const int t  = threadIdx.x;
    float v = d_gdot[bn*Mm + t] * boundary[b*Mm + t] * bweights[b*Mm + t];
#pragma unroll
    for (int o = 16; o > 0; o >>= 1) v += __shfl_down_sync(0xffffffffu, v, o);
    if ((t & 31) == 0) s2[t >> 5] = v;
    __syncthreads();
    if (t == 0) out[bn] = s2[0] + s2[1];
}

// =====================================================================
extern "C" void kernel_launch(void* const* d_in, const int* in_sizes, int n_in,
                              void* d_out, int out_size)
{
    const float* phase    = (const float*)d_in[0];
    const float* bcoords  = (const float*)d_in[1];
    const float* boundary = (const float*)d_in[2];
    const float* bweights = (const float*)d_in[3];
    const float* posc     = (const float*)d_in[4];
    const float* sigma    = (const float*)d_in[5];
    const float* velc     = (const float*)d_in[6];
    const float* vwt      = (const float*)d_in[7];
    const float* scat     = (const float*)d_in[8];
    const float* sscat    = (const float*)d_in[9];
    const float* aw0 = (const float*)d_in[10];
    const float* ab0 = (const float*)d_in[11];
    const float* aw1 = (const float*)d_in[12];
    const float* ab1 = (const float*)d_in[13];
    const float* aw2 = (const float*)d_in[14];
    const float* ab2 = (const float*)d_in[15];
    const float* tw0 = (const float*)d_in[16];
    const float* tb0 = (const float*)d_in[17];
    const float* tw1 = (const float*)d_in[18];
    const float* tb1 = (const float*)d_in[19];
    const float* tw2 = (const float*)d_in[20];
    const float* tb2 = (const float*)d_in[21];
    const float* sw0 = (const float*)d_in[22];
    const float* sb0 = (const float*)d_in[23];
    const float* sw1 = (const float*)d_in[24];
    const float* sb1 = (const float*)d_in[25];
    const float* ow  = (const float*)d_in[26];
    float* out = (float*)d_out;

    k_prep<<<128, 256>>>(tw1, tw2, sw0, sw1);
    k1_attn<<<Bb*Nn*K1, 128>>>(phase, posc, sigma, velc,
                               aw0, ab0, aw1, ab1, aw2, ab2, tw0, tb0);
    k_bm<<<Bb*Mm, TWd>>>(bcoords, tw0);
    k_h0<<<Bb*Nn*Mm, 128>>>();
    k_g1<<<NTILES, 256>>>(tb1);
    k_g2<<<NTILES, 256>>>(tb2);
    k5_scat<<<Bb*Nn*(Mm/2), 128>>>(scat, sscat, vwt, sb0, sb1, ow);
    k6_final<<<Bb*Nn, 64>>>(boundary, bweights, out);
}

// round 14
// speedup vs baseline: 1.5119x; 1.2264x over previous
#include <cuda_runtime.h>
#include <cuda_bf16.h>
#include <math.h>
#include <cstdint>

#define Bb 4
#define Nn 32
#define Mm 64
#define Kk 16
#define K1 17
#define Pp 128
#define Ww 128
#define TWd 256
#define NROWS (Bb*Nn*Mm*K1)      /* 139264 */
#define NTILES (NROWS/128)       /* 1088 */

typedef unsigned long long ull;

// ---------- f32x2 helpers ----------
__device__ __forceinline__ ull pack2(float a, float b) {
    ull r; asm("mov.b64 %0, {%1, %2};" : "=l"(r) : "f"(a), "f"(b)); return r;
}
__device__ __forceinline__ void unpack2(ull v, float& a, float& b) {
    asm("mov.b64 {%0, %1}, %2;" : "=f"(a), "=f"(b) : "l"(v));
}
__device__ __forceinline__ void fma2(ull& d, ull a, ull b) {
    asm("fma.rn.f32x2 %0, %1, %2, %0;" : "+l"(d) : "l"(a), "l"(b));
}
__device__ __forceinline__ ull add2(ull a, ull b) {
    ull r; asm("add.rn.f32x2 %0, %1, %2;" : "=l"(r) : "l"(a), "l"(b)); return r;
}
__device__ __forceinline__ float ftanh(float x) {
    float e = __expf(2.0f * x);
    return 1.0f - __fdividef(2.0f, e + 1.0f);
}
// bf16 split helpers
__device__ __forceinline__ unsigned short bfh(float x) {
    __nv_bfloat16 h = __float2bfloat16(x);
    return *reinterpret_cast<unsigned short*>(&h);
}
__device__ __forceinline__ unsigned short bfl(float x) {
    __nv_bfloat16 h = __float2bfloat16(x);
    float r = x - __bfloat162float(h);
    __nv_bfloat16 l = __float2bfloat16(r);
    return *reinterpret_cast<unsigned short*>(&l);
}
__device__ __forceinline__ unsigned packhi2(float a, float b) {
    return (unsigned)bfh(a) | ((unsigned)bfh(b) << 16);
}
__device__ __forceinline__ unsigned packlo2(float a, float b) {
    return (unsigned)bfl(a) | ((unsigned)bfl(b) << 16);
}
__device__ __forceinline__ uint32_t smem_to_u32(const void* p) {
    uint32_t a;
    asm("{ .reg .u64 tmp; cvta.to.shared.u64 tmp, %1; cvt.u32.u64 %0, tmp; }" : "=r"(a) : "l"(p));
    return a;
}
__device__ __forceinline__ void ldm_x4(uint32_t& r0, uint32_t& r1, uint32_t& r2, uint32_t& r3, uint32_t addr) {
    asm volatile("ldmatrix.sync.aligned.m8n8.x4.shared.b16 {%0,%1,%2,%3}, [%4];"
                 : "=r"(r0), "=r"(r1), "=r"(r2), "=r"(r3) : "r"(addr));
}
__device__ __forceinline__ void mma16816(float* c, const uint32_t* a, uint32_t b0, uint32_t b1) {
    asm volatile("mma.sync.aligned.m16n8k16.row.col.f32.bf16.bf16.f32 "
                 "{%0,%1,%2,%3}, {%4,%5,%6,%7}, {%8,%9}, {%0,%1,%2,%3};"
                 : "+f"(c[0]), "+f"(c[1]), "+f"(c[2]), "+f"(c[3])
                 : "r"(a[0]), "r"(a[1]), "r"(a[2]), "r"(a[3]), "r"(b0), "r"(b1));
}

// ------- scratch (device globals; no runtime allocation) -------
__device__ float d_A[Bb*Nn*K1*TWd];
__device__ float d_Bm[Bb*Mm*TWd];
__device__ float d_gdot[Bb*Nn*Mm];
__device__ float d_sw0T[Ww*Ww];             // [w][i]
__device__ float d_sw1T[Ww*Ww];             // [w][i]
__device__ unsigned d_W1hT[256*128];        // [n][kpair] bf16x2 (hi)
__device__ unsigned d_W1lT[256*128];        // (lo)
__device__ unsigned d_W2hT[128*128];
__device__ unsigned d_W2lT[128*128];
__device__ unsigned d_H1h[NROWS*128];
__device__ unsigned d_H1l[NROWS*128];
__device__ float    d_g [NROWS*128];

// =====================================================================
// K_prep: split-transposed weights + sw transposes
// =====================================================================
__global__ void k_prep(const float* __restrict__ tw1, const float* __restrict__ tw2,
                       const float* __restrict__ sw0, const float* __restrict__ sw1)
{
    const int idx = blockIdx.x*256 + threadIdx.x;   // 0..32767
    {
        const int n = idx >> 7, kp = idx & 127;
        const float w0 = tw1[(2*kp)*256 + n];
        const float w1 = tw1[(2*kp+1)*256 + n];
        d_W1hT[n*128 + kp] = packhi2(w0, w1);
        d_W1lT[n*128 + kp] = packlo2(w0, w1);
    }
    if (idx < 16384) {
        const int n = idx >> 7, kp = idx & 127;
        const float w0 = tw2[(2*kp)*128 + n];
        const float w1 = tw2[(2*kp+1)*128 + n];
        d_W2hT[n*128 + kp] = packhi2(w0, w1);
        d_W2lT[n*128 + kp] = packlo2(w0, w1);
        const int i = idx >> 7, w = idx & 127;
        d_sw0T[w*Ww + i] = sw0[idx];
        d_sw1T[w*Ww + i] = sw1[idx];
    }
}

// =====================================================================
// K1: attention MLP + softmax + coeff + A-partial.  One block per (b,n,k1).
// =====================================================================
__global__ void __launch_bounds__(128) k1_attn(
    const float* __restrict__ phase, const float* __restrict__ posc,
    const float* __restrict__ sigma, const float* __restrict__ velc,
    const float* __restrict__ aw0, const float* __restrict__ ab0,
    const float* __restrict__ aw1, const float* __restrict__ ab1,
    const float* __restrict__ aw2, const float* __restrict__ ab2,
    const float* __restrict__ tw0, const float* __restrict__ tb0)
{
    __shared__ float s_aw0[6*64];
    __shared__ float s_ab0[64];
    __shared__ float s_aw1[64*64];
    __shared__ float s_ab1[64];
    __shared__ float s_aw2[64];
    __shared__ float red[128];

    const int bx = blockIdx.x;
    const int k1 = bx % K1;
    const int n  = (bx / K1) % Nn;
    const int b  = bx / (K1*Nn);
    const int t  = threadIdx.x;

    for (int i = t; i < 6*64; i += 128) s_aw0[i] = aw0[i];
    if (t < 64) { s_ab0[t] = ab0[t]; s_aw2[t] = aw2[t]; s_ab1[t] = ab1[t]; }
    for (int i = t; i < 64*64; i += 128) s_aw1[i] = aw1[i];
    __syncthreads();

    const float x0 = phase[(b*Nn+n)*4 + 0];
    const float x1 = phase[(b*Nn+n)*4 + 1];
    float va0, va1;
    if (k1 == 0) { va0 = phase[(b*Nn+n)*4 + 2]; va1 = phase[(b*Nn+n)*4 + 3]; }
    else         { va0 = velc[(b*Kk + (k1-1))*2 + 0]; va1 = velc[(b*Kk + (k1-1))*2 + 1]; }
    const float inv = rsqrtf(va0*va0 + va1*va1 + 1e-16f);
    const float ag0 = va0*inv, ag1 = va1*inv;

    const float rx = x0 - posc[(b*Pp + t)*2 + 0];
    const float ry = x1 - posc[(b*Pp + t)*2 + 1];
    const float rd = sqrtf(rx*rx + ry*ry + 1e-16f);
    const float pl = rx*ag0 + ry*ag1;
    const float al = pl / (rd + 1e-8f);

    float h0[64];
#pragma unroll
    for (int j = 0; j < 64; j++) {
        h0[j] = ftanh(s_ab0[j] + x0*s_aw0[0*64+j] + x1*s_aw0[1*64+j]
                              + va0*s_aw0[2*64+j] + va1*s_aw0[3*64+j]
                              + al*s_aw0[4*64+j] + pl*s_aw0[5*64+j]);
    }
    float logit = ab2[0];
#pragma unroll
    for (int g = 0; g < 4; g++) {
        ull acc[8];
#pragma unroll
        for (int p = 0; p < 8; p++) acc[p] = 0ull;
        for (int j = 0; j < 64; j++) {
            const ull hp = pack2(h0[j], h0[j]);
            const float* wrow = &s_aw1[j*64 + g*16];
            ulonglong2 wA = *reinterpret_cast<const ulonglong2*>(wrow + 0);
            ulonglong2 wB = *reinterpret_cast<const ulonglong2*>(wrow + 4);
            ulonglong2 wC = *reinterpret_cast<const ulonglong2*>(wrow + 8);
            ulonglong2 wD = *reinterpret_cast<const ulonglong2*>(wrow + 12);
            fma2(acc[0], hp, wA.x); fma2(acc[1], hp, wA.y);
            fma2(acc[2], hp, wB.x); fma2(acc[3], hp, wB.y);
            fma2(acc[4], hp, wC.x); fma2(acc[5], hp, wC.y);
            fma2(acc[6], hp, wD.x); fma2(acc[7], hp, wD.y);
        }
#pragma unroll
        for (int p = 0; p < 8; p++) {
            const int i = g*16 + p*2;
            float a0, a1; unpack2(acc[p], a0, a1);
            logit += ftanh(a0 + s_ab1[i])   * s_aw2[i]
                   + ftanh(a1 + s_ab1[i+1]) * s_aw2[i+1];
        }
    }

    float lg = (pl > 0.0f) ? logit : -1e30f;
    red[t] = lg; __syncthreads();
    for (int s = 64; s > 0; s >>= 1) { if (t < s) red[t] = fmaxf(red[t], red[t+s]); __syncthreads(); }
    const float mx = red[0]; __syncthreads();
    const float e = __expf(lg - mx);
    red[t] = e; __syncthreads();
    for (int s = 64; s > 0; s >>= 1) { if (t < s) red[t] += red[t+s]; __syncthreads(); }
    const float denom = red[0]; __syncthreads();
    const float aw = e / denom;

    const float sg0 = sigma[(b*Pp+t)*2 + 0];
    const float sg1 = sigma[(b*Pp+t)*2 + 1];
    red[t] = aw*sg0; __syncthreads();
    for (int s = 64; s > 0; s >>= 1) { if (t < s) red[t] += red[t+s]; __syncthreads(); }
    const float sum0 = red[0]; __syncthreads();
    red[t] = aw*sg1; __syncthreads();
    for (int s = 64; s > 0; s >>= 1) { if (t < s) red[t] += red[t+s]; __syncthreads(); }
    const float sum1 = red[0]; __syncthreads();

    const float c0 = __expf(-sum0);
    const float c1 = __expf(-sum1);

    for (int tt = t; tt < TWd; tt += 128) {
        float a = tb0[tt]
                + x0*tw0[0*TWd+tt] + x1*tw0[1*TWd+tt]
                + va0*tw0[2*TWd+tt] + va1*tw0[3*TWd+tt]
                + c0*tw0[8*TWd+tt] + c1*tw0[9*TWd+tt];
        d_A[bx*TWd + tt] = a;
    }
}

// =====================================================================
__global__ void k_bm(const float* __restrict__ bcoords, const float* __restrict__ tw0)
{
    const int bm = blockIdx.x;
    const int t  = threadIdx.x;
    const float xp0 = bcoords[bm*4+0], xp1 = bcoords[bm*4+1];
    const float vp0 = bcoords[bm*4+2], vp1 = bcoords[bm*4+3];
    d_Bm[bm*TWd + t] = xp0*tw0[4*TWd+t] + xp1*tw0[5*TWd+t]
                     + vp0*tw0[6*TWd+t] + vp1*tw0[7*TWd+t];
}

// =====================================================================
// K_g1: H1 = tanh(H0 @ tw1 + tb1) via mma.sync bf16-split.
// H0 = tanh(A + Bm) computed ON THE FLY in the stage loads (A, Bm in L2).
// One stage-load per k-chunk feeds all 3 split terms.
// =====================================================================
__global__ void __launch_bounds__(256, 2) k_g1(const float* __restrict__ tb1)
{
    __shared__ unsigned A_h[128*12];       // [row][12] (8 used + 4 pad) bf16x2
    __shared__ unsigned A_l[128*12];
    __shared__ unsigned B_h[128*12];       // [n][12]
    __shared__ unsigned B_l[128*12];

    const int t   = threadIdx.x;
    const int lid = t & 31, wid = t >> 5;
    const int wm  = wid >> 2, wn = wid & 3;
    const int row0 = blockIdx.x * 128;
    const int lr = lid >> 2, lc = lid & 3;

    // precompute per-thread A/Bm row offsets for stage loads (i = 0..3)
    int aoff_[4], boff_[4];
#pragma unroll
    for (int i = 0; i < 4; i++) {
        const int idx = t + i*256;
        const int r = idx >> 3;
        const int row = row0 + r;
        const int bnm = row / 17;
        const int k   = row - bnm*17;
        const int bn  = bnm >> 6, m = bnm & 63;
        aoff_[i] = (bn*K1 + k)*256;
        boff_[i] = ((bn >> 5)*Mm + m)*256;
    }

    const uint32_t ah_base = smem_to_u32(A_h);
    const uint32_t al_base = smem_to_u32(A_l);
    const uint32_t bh_base = smem_to_u32(B_h);
    const uint32_t bl_base = smem_to_u32(B_l);
    const int arow  = wm*64 + (lid & 7) + ((lid >> 3) & 1)*8;
    const uint32_t a_off = (uint32_t)(arow*48 + ((lid >> 4)*8)*2);
    const int brow  = wn*32 + ((lid >> 4)*8) + (lid & 7);
    const uint32_t b_off = (uint32_t)(brow*48 + (((lid >> 3) & 1)*8)*2);

    for (int pass = 0; pass < 2; pass++) {
        float acc[4][4][4];
#pragma unroll
        for (int mi = 0; mi < 4; mi++)
#pragma unroll
            for (int ni = 0; ni < 4; ni++)
#pragma unroll
                for (int e = 0; e < 4; e++) acc[mi][ni][e] = 0.0f;

#pragma unroll 1
        for (int kc = 0; kc < 16; kc++) {
            __syncthreads();
#pragma unroll
            for (int i = 0; i < 4; i++) {
                const int idx = t + i*256;
                const int r = idx >> 3, j = idx & 7;
                const int cp = kc*8 + j;
                const float a0 = d_A[aoff_[i] + 2*cp];
                const float a1 = d_A[aoff_[i] + 2*cp + 1];
                const float b0 = d_Bm[boff_[i] + 2*cp];
                const float b1 = d_Bm[boff_[i] + 2*cp + 1];
                const float v0 = ftanh(a0 + b0);
                const float v1 = ftanh(a1 + b1);
                A_h[r*12 + j] = packhi2(v0, v1);
                A_l[r*12 + j] = packlo2(v0, v1);
                B_h[r*12 + j] = d_W1hT[(pass*128 + r)*128 + cp];
                B_l[r*12 + j] = d_W1lT[(pass*128 + r)*128 + cp];
            }
            __syncthreads();
            uint32_t ah[4][4];
#pragma unroll
            for (int mi = 0; mi < 4; mi++)
                ldm_x4(ah[mi][0], ah[mi][1], ah[mi][2], ah[mi][3], ah_base + a_off + (uint32_t)(mi*16*48));
            uint32_t bh[2][4], bl[2][4];
#pragma unroll
            for (int h = 0; h < 2; h++) {
                ldm_x4(bh[h][0], bh[h][1], bh[h][2], bh[h][3], bh_base + b_off + (uint32_t)(h*16*48));
                ldm_x4(bl[h][0], bl[h][1], bl[h][2], bl[h][3], bl_base + b_off + (uint32_t)(h*16*48));
            }
            // terms: hi*hi and hi*lo
#pragma unroll
            for (int mi = 0; mi < 4; mi++) {
#pragma unroll
                for (int ni = 0; ni < 4; ni++) {
                    const int h = ni >> 1, p = ni & 1;
                    mma16816(acc[mi][ni], ah[mi], bh[h][p*2], bh[h][p*2+1]);
                    mma16816(acc[mi][ni], ah[mi], bl[h][p*2], bl[h][p*2+1]);
                }
            }
            // term: lo*hi  (a_lo fragments as short-lived temps)
#pragma unroll
            for (int mi = 0; mi < 4; mi++) {
                uint32_t alf[4];
                ldm_x4(alf[0], alf[1], alf[2], alf[3], al_base + a_off + (uint32_t)(mi*16*48));
#pragma unroll
                for (int ni = 0; ni < 4; ni++) {
                    const int h = ni >> 1, p = ni & 1;
                    mma16816(acc[mi][ni], alf, bh[h][p*2], bh[h][p*2+1]);
                }
            }
        }

        // epilogue: tanh + bf16-split pack (layout identical to R13)
#pragma unroll
        for (int mi = 0; mi < 4; mi++) {
#pragma unroll
            for (int ni = 0; ni < 4; ni++) {
                const int r0 = row0 + wm*64 + mi*16 + lr;
                const int colg = pass*128 + wn*32 + ni*8 + 2*lc;
                const float bb0 = __ldg(&tb1[colg]);
                const float bb1 = __ldg(&tb1[colg+1]);
                const float t0 = ftanh(acc[mi][ni][0] + bb0);
                const float t1 = ftanh(acc[mi][ni][1] + bb1);
                const float t2 = ftanh(acc[mi][ni][2] + bb0);
                const float t3 = ftanh(acc[mi][ni][3] + bb1);
                const int cp = colg >> 1;
                d_H1h[r0*128 + cp]     = packhi2(t0, t1);
                d_H1l[r0*128 + cp]     = packlo2(t0, t1);
                d_H1h[(r0+8)*128 + cp] = packhi2(t2, t3);
                d_H1l[(r0+8)*128 + cp] = packlo2(t2, t3);
            }
        }
    }
}

// =====================================================================
// K_g2: g = exp(tanh(H1 @ tw2 + tb2)); single stage-load feeds 3 terms.
// =====================================================================
__global__ void __launch_bounds__(256, 2) k_g2(const float* __restrict__ tb2)
{
    __shared__ unsigned A_h[128*12];
    __shared__ unsigned A_l[128*12];
    __shared__ unsigned B_h[128*12];
    __shared__ unsigned B_l[128*12];

    const int t   = threadIdx.x;
    const int lid = t & 31, wid = t >> 5;
    const int wm  = wid >> 2, wn = wid & 3;
    const int row0 = blockIdx.x * 128;
    const int lr = lid >> 2, lc = lid & 3;

    const uint32_t ah_base = smem_to_u32(A_h);
    const uint32_t al_base = smem_to_u32(A_l);
    const uint32_t bh_base = smem_to_u32(B_h);
    const uint32_t bl_base = smem_to_u32(B_l);
    const int arow  = wm*64 + (lid & 7) + ((lid >> 3) & 1)*8;
    const uint32_t a_off = (uint32_t)(arow*48 + ((lid >> 4)*8)*2);
    const int brow  = wn*32 + ((lid >> 4)*8) + (lid & 7);
    const uint32_t b_off = (uint32_t)(brow*48 + (((lid >> 3) & 1)*8)*2);

    float acc[4][4][4];
#pragma unroll
    for (int mi = 0; mi < 4; mi++)
#pragma unroll
        for (int ni = 0; ni < 4; ni++)
#pragma unroll
            for (int e = 0; e < 4; e++) acc[mi][ni][e] = 0.0f;

#pragma unroll 1
    for (int kc = 0; kc < 16; kc++) {
        __syncthreads();
#pragma unroll
        for (int i = 0; i < 4; i++) {
            const int idx = t + i*256;
            const int r = idx >> 3, j = idx & 7;
            const int cp = kc*8 + j;
            A_h[r*12 + j] = d_H1h[(row0 + r)*128 + cp];
            A_l[r*12 + j] = d_H1l[(row0 + r)*128 + cp];
            B_h[r*12 + j] = d_W2hT[r*128 + cp];
            B_l[r*12 + j] = d_W2lT[r*128 + cp];
        }
        __syncthreads();
        uint32_t ah[4][4];
#pragma unroll
        for (int mi = 0; mi < 4; mi++)
            ldm_x4(ah[mi][0], ah[mi][1], ah[mi][2], ah[mi][3], ah_base + a_off + (uint32_t)(mi*16*48));
        uint32_t bh[2][4], bl[2][4];
#pragma unroll
        for (int h = 0; h < 2; h++) {
            ldm_x4(bh[h][0], bh[h][1], bh[h][2], bh[h][3], bh_base + b_off + (uint32_t)(h*16*48));
            ldm_x4(bl[h][0], bl[h][1], bl[h][2], bl[h][3], bl_base + b_off + (uint32_t)(h*16*48));
        }
#pragma unroll
        for (int mi = 0; mi < 4; mi++) {
#pragma unroll
            for (int ni = 0; ni < 4; ni++) {
                const int h = ni >> 1, p = ni & 1;
                mma16816(acc[mi][ni], ah[mi], bh[h][p*2], bh[h][p*2+1]);
                mma16816(acc[mi][ni], ah[mi], bl[h][p*2], bl[h][p*2+1]);
            }
        }
#pragma unroll
        for (int mi = 0; mi < 4; mi++) {
            uint32_t alf[4];
            ldm_x4(alf[0], alf[1], alf[2], alf[3], al_base + a_off + (uint32_t)(mi*16*48));
#pragma unroll
            for (int ni = 0; ni < 4; ni++) {
                const int h = ni >> 1, p = ni & 1;
                mma16816(acc[mi][ni], alf, bh[h][p*2], bh[h][p*2+1]);
            }
        }
    }

#pragma unroll
    for (int mi = 0; mi < 4; mi++) {
#pragma unroll
        for (int ni = 0; ni < 4; ni++) {
            const int r0 = row0 + wm*64 + mi*16 + lr;
            const int colg = wn*32 + ni*8 + 2*lc;
            const float bb0 = __ldg(&tb2[colg]);
            const float bb1 = __ldg(&tb2[colg+1]);
            float2 v0, v1;
            v0.x = __expf(ftanh(acc[mi][ni][0] + bb0));
            v0.y = __expf(ftanh(acc[mi][ni][1] + bb1));
            v1.x = __expf(ftanh(acc[mi][ni][2] + bb0));
            v1.y = __expf(ftanh(acc[mi][ni][3] + bb1));
            *reinterpret_cast<float2*>(&d_g[r0*128 + colg])     = v0;
            *reinterpret_cast<float2*>(&d_g[(r0+8)*128 + colg]) = v1;
        }
    }
}

// =====================================================================
// K5: scattering chain on g (f32x2 over the m-pair), per (b,n,m-pair).
// =====================================================================
__global__ void __launch_bounds__(128) k5_scat(
    const float* __restrict__ scat, const float* __restrict__ sscat,
    const float* __restrict__ vwt,
    const float* __restrict__ sb0, const float* __restrict__ sb1,
    const float* __restrict__ out_w)
{
    __shared__ float buf[8704];      // g(17x256 pairs) | rr(17x256) at +4352
    __shared__ ull   ws2[272];
    __shared__ float sres[256];
    __shared__ float sred[8];

    const int bx   = blockIdx.x;              // 0..4095
    const int pair = bx & 31;
    const int n    = (bx >> 5) & 31;
    const int b    = bx >> 10;
    const int t    = threadIdx.x;
    const int th   = t >> 6;
    const int tc   = t & 63;
    const int kbs  = th ? 9 : 0;
    const int kcs  = th ? 8 : 9;

    for (int i = t; i < 272; i += 128) {
        const int row = i >> 4, j = i & 15;
        float v = (row == 0) ? (1.0f - scat[(b*Nn+n)*Kk + j])
                             : (1.0f - sscat[b*256 + (row-1)*Kk + j]);
        v *= vwt[b*Kk + j];
        ws2[i] = pack2(v, v);
    }

    const int bnm0 = ((b*Nn + n)*Mm + pair*2);
#pragma unroll
    for (int k = 0; k < K1; k++) {
        const float g0 = d_g[(bnm0*K1 + k)*128 + t];
        const float g1 = d_g[((bnm0+1)*K1 + k)*128 + t];
        *reinterpret_cast<ull*>(buf + k*256 + 2*t) = pack2(g0, g1);
    }
    __syncthreads();

    const float sb0a = sb0[tc], sb0b = sb0[tc+64];
    const float sb1c = sb1[t];
    const float owc  = out_w[t];

    // ---- stage 1: rr[k] = sum_j ws2[k][j]*g[1+j] ----
    {
        ull g2r[Kk];
#pragma unroll
        for (int j = 0; j < Kk; j++)
            g2r[j] = *reinterpret_cast<const ull*>(buf + (1+j)*256 + 2*t);
#pragma unroll
        for (int k = 0; k < K1; k++) {
            ull r = 0ull;
            const ulonglong2* wsp = reinterpret_cast<const ulonglong2*>(ws2 + k*Kk);
#pragma unroll
            for (int jp = 0; jp < 8; jp++) {
                const ulonglong2 wv = wsp[jp];
                fma2(r, g2r[2*jp],   wv.x);
                fma2(r, g2r[2*jp+1], wv.y);
            }
            *reinterpret_cast<ull*>(buf + 4352 + k*256 + 2*t) = r;
        }
        __syncthreads();
    }

    // ---- stage 2: g[k][c] += tanh(sw0T[:,c]@rr[k][:] + sb0[c]); k-split, 2 cols ----
    {
        ull sA[9], sB[9];
#pragma unroll
        for (int k = 0; k < 9; k++) { sA[k] = 0ull; sB[k] = 0ull; }
        const float* wb = d_sw0T + tc;
        float wcA[4], wcB[4], wnA[4], wnB[4];
#pragma unroll
        for (int ww = 0; ww < 4; ww++) { wcA[ww] = wb[ww*Ww]; wcB[ww] = wb[ww*Ww + 64]; }
#pragma unroll 1
        for (int w = 0; w < Ww; w += 4) {
            if (w + 4 < Ww) {
                const float* wp = wb + (w+4)*Ww;
#pragma unroll
                for (int ww = 0; ww < 4; ww++) { wnA[ww] = wp[ww*Ww]; wnB[ww] = wp[ww*Ww + 64]; }
            }
            const ull pA0 = pack2(wcA[0],wcA[0]), pA1 = pack2(wcA[1],wcA[1]),
                      pA2 = pack2(wcA[2],wcA[2]), pA3 = pack2(wcA[3],wcA[3]);
            const ull pB0 = pack2(wcB[0],wcB[0]), pB1 = pack2(wcB[1],wcB[1]),
                      pB2 = pack2(wcB[2],wcB[2]), pB3 = pack2(wcB[3],wcB[3]);
#pragma unroll
            for (int k = 0; k < 9; k++) {
                if (k < kcs) {
                    ulonglong2 ra = *reinterpret_cast<const ulonglong2*>(buf + 4352 + (kbs+k)*256 + w*2);
                    ulonglong2 rb = *reinterpret_cast<const ulonglong2*>(buf + 4352 + (kbs+k)*256 + w*2 + 4);
                    fma2(sA[k], ra.x, pA0); fma2(sA[k], ra.y, pA1);
                    fma2(sA[k], rb.x, pA2); fma2(sA[k], rb.y, pA3);
                    fma2(sB[k], ra.x, pB0); fma2(sB[k], ra.y, pB1);
                    fma2(sB[k], rb.x, pB2); fma2(sB[k], rb.y, pB3);
                }
            }
#pragma unroll
            for (int q = 0; q < 4; q++) { wcA[q] = wnA[q]; wcB[q] = wnB[q]; }
        }
#pragma unroll
        for (int k = 0; k < 9; k++) {
            if (k < kcs) {
                float a0, a1; unpack2(sA[k], a0, a1);
                ull* gp = reinterpret_cast<ull*>(buf + (kbs+k)*256 + 2*tc);
                float g0, g1; unpack2(*gp, g0, g1);
                *gp = pack2(g0 + ftanh(a0+sb0a), g1 + ftanh(a1+sb0a));
                unpack2(sB[k], a0, a1);
                gp = reinterpret_cast<ull*>(buf + (kbs+k)*256 + 2*(tc+64));
                unpack2(*gp, g0, g1);
                *gp = pack2(g0 + ftanh(a0+sb0b), g1 + ftanh(a1+sb0b));
            }
        }
        __syncthreads();
    }

    // ---- stage 3 ----
    {
        ull rv = 0ull;
#pragma unroll
        for (int k = 0; k < Kk; k++)
            fma2(rv, *reinterpret_cast<const ull*>(buf + (1+k)*256 + 2*t), ws2[k]);
        *reinterpret_cast<ull*>(sres + 2*t) = rv;
    }
    __syncthreads();

    // ---- stage 4 ----
    {
        ull sa = 0ull, sb = 0ull;
        const float* wb = d_sw1T + t;
#pragma unroll 1
        for (int w = 0; w < Ww; w += 4) {
            const float v0w = wb[(w+0)*Ww];
            const float v1w = wb[(w+1)*Ww];
            const float v2w = wb[(w+2)*Ww];
            const float v3w = wb[(w+3)*Ww];
            ulonglong2 ra = *reinterpret_cast<const ulonglong2*>(sres + w*2);
            ulonglong2 rb = *reinterpret_cast<const ulonglong2*>(sres + w*2 + 4);
            fma2(sa, ra.x, pack2(v0w,v0w)); fma2(sb, ra.y, pack2(v1w,v1w));
            fma2(sa, rb.x, pack2(v2w,v2w)); fma2(sb, rb.y, pack2(v3w,v3w));
        }
        const ull tot = add2(sa, sb);
        float a0, a1; unpack2(tot, a0, a1);
        float v0, v1; unpack2(*reinterpret_cast<const ull*>(buf + 2*t), v0, v1);
        float p0 = (v0 + ftanh(a0+sb1c)) * owc;
        float p1 = (v1 + ftanh(a1+sb1c)) * owc;
#pragma unroll
        for (int o = 16; o > 0; o >>= 1) {
            p0 += __shfl_down_sync(0xffffffffu, p0, o);
            p1 += __shfl_down_sync(0xffffffffu, p1, o);
        }
        if ((t & 31) == 0) { sred[(t>>5)*2] = p0; sred[(t>>5)*2+1] = p1; }
        __syncthreads();
        if (t == 0) {
            d_gdot[(b*Nn+n)*Mm + pair*2 + 0] = sred[0]+sred[2]+sred[4]+sred[6];
            d_gdot[(b*Nn+n)*Mm + pair*2 + 1] = sred[1]+sred[3]+sred[5]+sred[7];
        }
    }
}

// =====================================================================
__global__ void k6_final(const float* __restrict__ boundary,
                         const float* __restrict__ bweights,
                         float* __restrict__ out)
{
    __shared__ float s2[2];
    const int bn = blockIdx.x;
    const int b  = bn >> 5;
    const int t  = threadIdx.x;
    float v = d_gdot[bn*Mm + t] * boundary[b*Mm + t] * bweights[b*Mm + t];
#pragma unroll
    for (int o = 16; o > 0; o >>= 1) v += __shfl_down_sync(0xffffffffu, v, o);
    if ((t & 31) == 0) s2[t >> 5] = v;
    __syncthreads();
    if (t == 0) out[bn] = s2[0] + s2[1];
}

// =====================================================================
extern "C" void kernel_launch(void* const* d_in, const int* in_sizes, int n_in,
                              void* d_out, int out_size)
{
    const float* phase    = (const float*)d_in[0];
    const float* bcoords  = (const float*)d_in[1];
    const float* boundary = (const float*)d_in[2];
    const float* bweights = (const float*)d_in[3];
    const float* posc     = (const float*)d_in[4];
    const float* sigma    = (const float*)d_in[5];
    const float* velc     = (const float*)d_in[6];
    const float* vwt      = (const float*)d_in[7];
    const float* scat     = (const float*)d_in[8];
    const float* sscat    = (const float*)d_in[9];
    const float* aw0 = (const float*)d_in[10];
    const float* ab0 = (const float*)d_in[11];
    const float* aw1 = (const float*)d_in[12];
    const float* ab1 = (const float*)d_in[13];
    const float* aw2 = (const float*)d_in[14];
    const float* ab2 = (const float*)d_in[15];
    const float* tw0 = (const float*)d_in[16];
    const float* tb0 = (const float*)d_in[17];
    const float* tw1 = (const float*)d_in[18];
    const float* tb1 = (const float*)d_in[19];
    const float* tw2 = (const float*)d_in[20];
    const float* tb2 = (const float*)d_in[21];
    const float* sw0 = (const float*)d_in[22];
    const float* sb0 = (const float*)d_in[23];
    const float* sw1 = (const float*)d_in[24];
    const float* sb1 = (const float*)d_in[25];
    const float* ow  = (const float*)d_in[26];
    float* out = (float*)d_out;

    k_prep<<<128, 256>>>(tw1, tw2, sw0, sw1);
    k1_attn<<<Bb*Nn*K1, 128>>>(phase, posc, sigma, velc,
                               aw0, ab0, aw1, ab1, aw2, ab2, tw0, tb0);
    k_bm<<<Bb*Mm, TWd>>>(bcoords, tw0);
    k_g1<<<NTILES, 256>>>(tb1);
    k_g2<<<NTILES, 256>>>(tb2);
    k5_scat<<<Bb*Nn*(Mm/2), 128>>>(scat, sscat, vwt, sb0, sb1, ow);
    k6_final<<<Bb*Nn, 64>>>(boundary, bweights, out);
}

// round 15
// speedup vs baseline: 1.5542x; 1.0280x over previous
#include <cuda_runtime.h>
#include <cuda_bf16.h>
#include <math.h>
#include <cstdint>

#define Bb 4
#define Nn 32
#define Mm 64
#define Kk 16
#define K1 17
#define Pp 128
#define Ww 128
#define TWd 256
#define NROWS (Bb*Nn*Mm*K1)      /* 139264 */
#define NTILES (NROWS/128)       /* 1088 */

typedef unsigned long long ull;

// ---------- f32x2 helpers ----------
__device__ __forceinline__ ull pack2(float a, float b) {
    ull r; asm("mov.b64 %0, {%1, %2};" : "=l"(r) : "f"(a), "f"(b)); return r;
}
__device__ __forceinline__ void unpack2(ull v, float& a, float& b) {
    asm("mov.b64 {%0, %1}, %2;" : "=f"(a), "=f"(b) : "l"(v));
}
__device__ __forceinline__ void fma2(ull& d, ull a, ull b) {
    asm("fma.rn.f32x2 %0, %1, %2, %0;" : "+l"(d) : "l"(a), "l"(b));
}
__device__ __forceinline__ ull add2(ull a, ull b) {
    ull r; asm("add.rn.f32x2 %0, %1, %2;" : "=l"(r) : "l"(a), "l"(b)); return r;
}
__device__ __forceinline__ float ftanh(float x) {
    float e = __expf(2.0f * x);
    return 1.0f - __fdividef(2.0f, e + 1.0f);
}
// bf16 split helpers
__device__ __forceinline__ unsigned short bfh(float x) {
    __nv_bfloat16 h = __float2bfloat16(x);
    return *reinterpret_cast<unsigned short*>(&h);
}
__device__ __forceinline__ unsigned short bfl(float x) {
    __nv_bfloat16 h = __float2bfloat16(x);
    float r = x - __bfloat162float(h);
    __nv_bfloat16 l = __float2bfloat16(r);
    return *reinterpret_cast<unsigned short*>(&l);
}
__device__ __forceinline__ unsigned packhi2(float a, float b) {
    return (unsigned)bfh(a) | ((unsigned)bfh(b) << 16);
}
__device__ __forceinline__ unsigned packlo2(float a, float b) {
    return (unsigned)bfl(a) | ((unsigned)bfl(b) << 16);
}
__device__ __forceinline__ uint32_t smem_to_u32(const void* p) {
    uint32_t a;
    asm("{ .reg .u64 tmp; cvta.to.shared.u64 tmp, %1; cvt.u32.u64 %0, tmp; }" : "=r"(a) : "l"(p));
    return a;
}
__device__ __forceinline__ void ldm_x4(uint32_t& r0, uint32_t& r1, uint32_t& r2, uint32_t& r3, uint32_t addr) {
    asm volatile("ldmatrix.sync.aligned.m8n8.x4.shared.b16 {%0,%1,%2,%3}, [%4];"
                 : "=r"(r0), "=r"(r1), "=r"(r2), "=r"(r3) : "r"(addr));
}
__device__ __forceinline__ void mma16816(float* c, const uint32_t* a, uint32_t b0, uint32_t b1) {
    asm volatile("mma.sync.aligned.m16n8k16.row.col.f32.bf16.bf16.f32 "
                 "{%0,%1,%2,%3}, {%4,%5,%6,%7}, {%8,%9}, {%0,%1,%2,%3};"
                 : "+f"(c[0]), "+f"(c[1]), "+f"(c[2]), "+f"(c[3])
                 : "r"(a[0]), "r"(a[1]), "r"(a[2]), "r"(a[3]), "r"(b0), "r"(b1));
}
__device__ __forceinline__ void cp16(uint32_t saddr, const void* gaddr) {
    asm volatile("cp.async.cg.shared.global [%0], [%1], 16;" :: "r"(saddr), "l"(gaddr));
}
#define CP_COMMIT() asm volatile("cp.async.commit_group;" ::: "memory")
#define CP_WAIT(n)  asm volatile("cp.async.wait_group %0;" :: "n"(n) : "memory")

// ------- scratch (device globals; no runtime allocation) -------
__device__ float d_A[Bb*Nn*K1*TWd];
__device__ float d_Bm[Bb*Mm*TWd];
__device__ float d_gdot[Bb*Nn*Mm];
__device__ float d_sw0T[Ww*Ww];             // [w][i]
__device__ float d_sw1T[Ww*Ww];             // [w][i]
__device__ unsigned d_W1hT[256*128];        // [n][kpair] bf16x2 (hi)
__device__ unsigned d_W1lT[256*128];        // (lo)
__device__ unsigned d_W2hT[128*128];
__device__ unsigned d_W2lT[128*128];
__device__ unsigned d_H0h[NROWS*128];
__device__ unsigned d_H0l[NROWS*128];
__device__ unsigned d_H1h[NROWS*128];
__device__ unsigned d_H1l[NROWS*128];
__device__ float    d_g [NROWS*128];

// =====================================================================
// K_prep: split-transposed weights + sw transposes
// =====================================================================
__global__ void k_prep(const float* __restrict__ tw1, const float* __restrict__ tw2,
                       const float* __restrict__ sw0, const float* __restrict__ sw1)
{
    const int idx = blockIdx.x*256 + threadIdx.x;   // 0..32767
    {
        const int n = idx >> 7, kp = idx & 127;
        const float w0 = tw1[(2*kp)*256 + n];
        const float w1 = tw1[(2*kp+1)*256 + n];
        d_W1hT[n*128 + kp] = packhi2(w0, w1);
        d_W1lT[n*128 + kp] = packlo2(w0, w1);
    }
    if (idx < 16384) {
        const int n = idx >> 7, kp = idx & 127;
        const float w0 = tw2[(2*kp)*128 + n];
        const float w1 = tw2[(2*kp+1)*128 + n];
        d_W2hT[n*128 + kp] = packhi2(w0, w1);
        d_W2lT[n*128 + kp] = packlo2(w0, w1);
        const int i = idx >> 7, w = idx & 127;
        d_sw0T[w*Ww + i] = sw0[idx];
        d_sw1T[w*Ww + i] = sw1[idx];
    }
}

// =====================================================================
// K1: attention MLP + softmax + coeff + A-partial.  One block per (b,n,k1).
// =====================================================================
__global__ void __launch_bounds__(128) k1_attn(
    const float* __restrict__ phase, const float* __restrict__ posc,
    const float* __restrict__ sigma, const float* __restrict__ velc,
    const float* __restrict__ aw0, const float* __restrict__ ab0,
    const float* __restrict__ aw1, const float* __restrict__ ab1,
    const float* __restrict__ aw2, const float* __restrict__ ab2,
    const float* __restrict__ tw0, const float* __restrict__ tb0)
{
    __shared__ float s_aw0[6*64];
    __shared__ float s_ab0[64];
    __shared__ float s_aw1[64*64];
    __shared__ float s_ab1[64];
    __shared__ float s_aw2[64];
    __shared__ float red[128];

    const int bx = blockIdx.x;
    const int k1 = bx % K1;
    const int n  = (bx / K1) % Nn;
    const int b  = bx / (K1*Nn);
    const int t  = threadIdx.x;

    for (int i = t; i < 6*64; i += 128) s_aw0[i] = aw0[i];
    if (t < 64) { s_ab0[t] = ab0[t]; s_aw2[t] = aw2[t]; s_ab1[t] = ab1[t]; }
    for (int i = t; i < 64*64; i += 128) s_aw1[i] = aw1[i];
    __syncthreads();

    const float x0 = phase[(b*Nn+n)*4 + 0];
    const float x1 = phase[(b*Nn+n)*4 + 1];
    float va0, va1;
    if (k1 == 0) { va0 = phase[(b*Nn+n)*4 + 2]; va1 = phase[(b*Nn+n)*4 + 3]; }
    else         { va0 = velc[(b*Kk + (k1-1))*2 + 0]; va1 = velc[(b*Kk + (k1-1))*2 + 1]; }
    const float inv = rsqrtf(va0*va0 + va1*va1 + 1e-16f);
    const float ag0 = va0*inv, ag1 = va1*inv;

    const float rx = x0 - posc[(b*Pp + t)*2 + 0];
    const float ry = x1 - posc[(b*Pp + t)*2 + 1];
    const float rd = sqrtf(rx*rx + ry*ry + 1e-16f);
    const float pl = rx*ag0 + ry*ag1;
    const float al = pl / (rd + 1e-8f);

    float h0[64];
#pragma unroll
    for (int j = 0; j < 64; j++) {
        h0[j] = ftanh(s_ab0[j] + x0*s_aw0[0*64+j] + x1*s_aw0[1*64+j]
                              + va0*s_aw0[2*64+j] + va1*s_aw0[3*64+j]
                              + al*s_aw0[4*64+j] + pl*s_aw0[5*64+j]);
    }
    float logit = ab2[0];
#pragma unroll
    for (int g = 0; g < 4; g++) {
        ull acc[8];
#pragma unroll
        for (int p = 0; p < 8; p++) acc[p] = 0ull;
        for (int j = 0; j < 64; j++) {
            const ull hp = pack2(h0[j], h0[j]);
            const float* wrow = &s_aw1[j*64 + g*16];
            ulonglong2 wA = *reinterpret_cast<const ulonglong2*>(wrow + 0);
            ulonglong2 wB = *reinterpret_cast<const ulonglong2*>(wrow + 4);
            ulonglong2 wC = *reinterpret_cast<const ulonglong2*>(wrow + 8);
            ulonglong2 wD = *reinterpret_cast<const ulonglong2*>(wrow + 12);
            fma2(acc[0], hp, wA.x); fma2(acc[1], hp, wA.y);
            fma2(acc[2], hp, wB.x); fma2(acc[3], hp, wB.y);
            fma2(acc[4], hp, wC.x); fma2(acc[5], hp, wC.y);
            fma2(acc[6], hp, wD.x); fma2(acc[7], hp, wD.y);
        }
#pragma unroll
        for (int p = 0; p < 8; p++) {
            const int i = g*16 + p*2;
            float a0, a1; unpack2(acc[p], a0, a1);
            logit += ftanh(a0 + s_ab1[i])   * s_aw2[i]
                   + ftanh(a1 + s_ab1[i+1]) * s_aw2[i+1];
        }
    }

    float lg = (pl > 0.0f) ? logit : -1e30f;
    red[t] = lg; __syncthreads();
    for (int s = 64; s > 0; s >>= 1) { if (t < s) red[t] = fmaxf(red[t], red[t+s]); __syncthreads(); }
    const float mx = red[0]; __syncthreads();
    const float e = __expf(lg - mx);
    red[t] = e; __syncthreads();
    for (int s = 64; s > 0; s >>= 1) { if (t < s) red[t] += red[t+s]; __syncthreads(); }
    const float denom = red[0]; __syncthreads();
    const float aw = e / denom;

    const float sg0 = sigma[(b*Pp+t)*2 + 0];
    const float sg1 = sigma[(b*Pp+t)*2 + 1];
    red[t] = aw*sg0; __syncthreads();
    for (int s = 64; s > 0; s >>= 1) { if (t < s) red[t] += red[t+s]; __syncthreads(); }
    const float sum0 = red[0]; __syncthreads();
    red[t] = aw*sg1; __syncthreads();
    for (int s = 64; s > 0; s >>= 1) { if (t < s) red[t] += red[t+s]; __syncthreads(); }
    const float sum1 = red[0]; __syncthreads();

    const float c0 = __expf(-sum0);
    const float c1 = __expf(-sum1);

    for (int tt = t; tt < TWd; tt += 128) {
        float a = tb0[tt]
                + x0*tw0[0*TWd+tt] + x1*tw0[1*TWd+tt]
                + va0*tw0[2*TWd+tt] + va1*tw0[3*TWd+tt]
                + c0*tw0[8*TWd+tt] + c1*tw0[9*TWd+tt];
        d_A[bx*TWd + tt] = a;
    }
}

// =====================================================================
__global__ void k_bm(const float* __restrict__ bcoords, const float* __restrict__ tw0)
{
    const int bm = blockIdx.x;
    const int t  = threadIdx.x;
    const float xp0 = bcoords[bm*4+0], xp1 = bcoords[bm*4+1];
    const float vp0 = bcoords[bm*4+2], vp1 = bcoords[bm*4+3];
    d_Bm[bm*TWd + t] = xp0*tw0[4*TWd+t] + xp1*tw0[5*TWd+t]
                     + vp0*tw0[6*TWd+t] + vp1*tw0[7*TWd+t];
}

// =====================================================================
// K_h0: H0 = tanh(A + Bm) as bf16-split pair arrays.  Block per (b,n,m).
// =====================================================================
__global__ void __launch_bounds__(128) k_h0()
{
    const int bnm = blockIdx.x;            // 0..8191
    const int m   = bnm & 63;
    const int bn  = bnm >> 6;              // b*32+n
    const int t   = threadIdx.x;           // pair index 0..127
    const float* Arow = d_A + bn*K1*TWd;
    const float* Bm   = d_Bm + ((bn >> 5)*Mm + m)*TWd;
    const float bm0 = Bm[2*t], bm1 = Bm[2*t+1];
#pragma unroll
    for (int k = 0; k < K1; k++) {
        const float v0 = ftanh(Arow[k*TWd + 2*t]     + bm0);
        const float v1 = ftanh(Arow[k*TWd + 2*t + 1] + bm1);
        const int o = (bnm*K1 + k)*128 + t;
        d_H0h[o] = packhi2(v0, v1);
        d_H0l[o] = packlo2(v0, v1);
    }
}

// =====================================================================
// K_g1: H1 = tanh(H0 @ tw1 + tb1).  cp.async double-buffered stages.
// stage[buf][arr][128*12], arr: 0=A_h 1=A_l 2=B_h 3=B_l.  48KB total.
// =====================================================================
__global__ void __launch_bounds__(256, 2) k_g1(const float* __restrict__ tb1)
{
    __shared__ unsigned stage[2][4][128*12];

    const int t   = threadIdx.x;
    const int lid = t & 31, wid = t >> 5;
    const int wm  = wid >> 2, wn = wid & 3;
    const int row0 = blockIdx.x * 128;
    const int lr = lid >> 2, lc = lid & 3;

    // stage-copy mapping: thread -> (row r, 16B group j4)
    const int cr = t >> 1, cj4 = t & 1;
    const uint32_t s_base = smem_to_u32(stage);
    const uint32_t cp_off = (uint32_t)((cr*12 + cj4*4)*4);

    const int arow  = wm*64 + (lid & 7) + ((lid >> 3) & 1)*8;
    const uint32_t a_off = (uint32_t)(arow*48 + ((lid >> 4)*8)*2);
    const int brow  = wn*32 + ((lid >> 4)*8) + (lid & 7);
    const uint32_t b_off = (uint32_t)(brow*48 + (((lid >> 3) & 1)*8)*2);
    const uint32_t BUF = 4u*128u*12u*4u;   // bytes per buffer
    const uint32_t ARR = 128u*12u*4u;      // bytes per array

    for (int pass = 0; pass < 2; pass++) {
        float acc[4][4][4];
#pragma unroll
        for (int mi = 0; mi < 4; mi++)
#pragma unroll
            for (int ni = 0; ni < 4; ni++)
#pragma unroll
                for (int e = 0; e < 4; e++) acc[mi][ni][e] = 0.0f;

        // prologue: prefetch chunk 0 into buf 0
        {
            const int cp = 0*8 + cj4*4;
            cp16(s_base + 0*BUF + 0*ARR + cp_off, &d_H0h[(row0 + cr)*128 + cp]);
            cp16(s_base + 0*BUF + 1*ARR + cp_off, &d_H0l[(row0 + cr)*128 + cp]);
            cp16(s_base + 0*BUF + 2*ARR + cp_off, &d_W1hT[(pass*128 + cr)*128 + cp]);
            cp16(s_base + 0*BUF + 3*ARR + cp_off, &d_W1lT[(pass*128 + cr)*128 + cp]);
            CP_COMMIT();
        }

#pragma unroll 1
        for (int kc = 0; kc < 16; kc++) {
            if (kc + 1 < 16) {
                const uint32_t bs = s_base + (uint32_t)((kc+1) & 1)*BUF;
                const int cp = (kc+1)*8 + cj4*4;
                cp16(bs + 0*ARR + cp_off, &d_H0h[(row0 + cr)*128 + cp]);
                cp16(bs + 1*ARR + cp_off, &d_H0l[(row0 + cr)*128 + cp]);
                cp16(bs + 2*ARR + cp_off, &d_W1hT[(pass*128 + cr)*128 + cp]);
                cp16(bs + 3*ARR + cp_off, &d_W1lT[(pass*128 + cr)*128 + cp]);
                CP_COMMIT();
                CP_WAIT(1);
            } else {
                CP_WAIT(0);
            }
            __syncthreads();

            const uint32_t bs = s_base + (uint32_t)(kc & 1)*BUF;
            uint32_t ah[4][4];
#pragma unroll
            for (int mi = 0; mi < 4; mi++)
                ldm_x4(ah[mi][0], ah[mi][1], ah[mi][2], ah[mi][3],
                       bs + 0*ARR + a_off + (uint32_t)(mi*16*48));
            uint32_t bh[2][4], bl[2][4];
#pragma unroll
            for (int h = 0; h < 2; h++) {
                ldm_x4(bh[h][0], bh[h][1], bh[h][2], bh[h][3],
                       bs + 2*ARR + b_off + (uint32_t)(h*16*48));
                ldm_x4(bl[h][0], bl[h][1], bl[h][2], bl[h][3],
                       bs + 3*ARR + b_off + (uint32_t)(h*16*48));
            }
#pragma unroll
            for (int mi = 0; mi < 4; mi++) {
#pragma unroll
                for (int ni = 0; ni < 4; ni++) {
                    const int h = ni >> 1, p = ni & 1;
                    mma16816(acc[mi][ni], ah[mi], bh[h][p*2], bh[h][p*2+1]);
                    mma16816(acc[mi][ni], ah[mi], bl[h][p*2], bl[h][p*2+1]);
                }
            }
#pragma unroll
            for (int mi = 0; mi < 4; mi++) {
                uint32_t alf[4];
                ldm_x4(alf[0], alf[1], alf[2], alf[3],
                       bs + 1*ARR + a_off + (uint32_t)(mi*16*48));
#pragma unroll
                for (int ni = 0; ni < 4; ni++) {
                    const int h = ni >> 1, p = ni & 1;
                    mma16816(acc[mi][ni], alf, bh[h][p*2], bh[h][p*2+1]);
                }
            }
            __syncthreads();
        }

        // epilogue: tanh + bf16-split pack (layout identical to R13/R14)
#pragma unroll
        for (int mi = 0; mi < 4; mi++) {
#pragma unroll
            for (int ni = 0; ni < 4; ni++) {
                const int r0 = row0 + wm*64 + mi*16 + lr;
                const int colg = pass*128 + wn*32 + ni*8 + 2*lc;
                const float bb0 = __ldg(&tb1[colg]);
                const float bb1 = __ldg(&tb1[colg+1]);
                const float t0 = ftanh(acc[mi][ni][0] + bb0);
                const float t1 = ftanh(acc[mi][ni][1] + bb1);
                const float t2 = ftanh(acc[mi][ni][2] + bb0);
                const float t3 = ftanh(acc[mi][ni][3] + bb1);
                const int cp = colg >> 1;
                d_H1h[r0*128 + cp]     = packhi2(t0, t1);
                d_H1l[r0*128 + cp]     = packlo2(t0, t1);
                d_H1h[(r0+8)*128 + cp] = packhi2(t2, t3);
                d_H1l[(r0+8)*128 + cp] = packlo2(t2, t3);
            }
        }
        __syncthreads();
    }
}

// =====================================================================
// K_g2: g = exp(tanh(H1 @ tw2 + tb2)).  Same cp.async pipeline, 1 pass.
// =====================================================================
__global__ void __launch_bounds__(256, 2) k_g2(const float* __restrict__ tb2)
{
    __shared__ unsigned stage[2][4][128*12];

    const int t   = threadIdx.x;
    const int lid = t & 31, wid = t >> 5;
    const int wm  = wid >> 2, wn = wid & 3;
    const int row0 = blockIdx.x * 128;
    const int lr = lid >> 2, lc = lid & 3;

    const int cr = t >> 1, cj4 = t & 1;
    const uint32_t s_base = smem_to_u32(stage);
    const uint32_t cp_off = (uint32_t)((cr*12 + cj4*4)*4);

    const int arow  = wm*64 + (lid & 7) + ((lid >> 3) & 1)*8;
    const uint32_t a_off = (uint32_t)(arow*48 + ((lid >> 4)*8)*2);
    const int brow  = wn*32 + ((lid >> 4)*8) + (lid & 7);
    const uint32_t b_off = (uint32_t)(brow*48 + (((lid >> 3) & 1)*8)*2);
    const uint32_t BUF = 4u*128u*12u*4u;
    const uint32_t ARR = 128u*12u*4u;

    float acc[4][4][4];
#pragma unroll
    for (int mi = 0; mi < 4; mi++)
#pragma unroll
        for (int ni = 0; ni < 4; ni++)
#pragma unroll
            for (int e = 0; e < 4; e++) acc[mi][ni][e] = 0.0f;

    {
        const int cp = cj4*4;
        cp16(s_base + 0*BUF + 0*ARR + cp_off, &d_H1h[(row0 + cr)*128 + cp]);
        cp16(s_base + 0*BUF + 1*ARR + cp_off, &d_H1l[(row0 + cr)*128 + cp]);
        cp16(s_base + 0*BUF + 2*ARR + cp_off, &d_W2hT[cr*128 + cp]);
        cp16(s_base + 0*BUF + 3*ARR + cp_off, &d_W2lT[cr*128 + cp]);
        CP_COMMIT();
    }

#pragma unroll 1
    for (int kc = 0; kc < 16; kc++) {
        if (kc + 1 < 16) {
            const uint32_t bs = s_base + (uint32_t)((kc+1) & 1)*BUF;
            const int cp = (kc+1)*8 + cj4*4;
            cp16(bs + 0*ARR + cp_off, &d_H1h[(row0 + cr)*128 + cp]);
            cp16(bs + 1*ARR + cp_off, &d_H1l[(row0 + cr)*128 + cp]);
            cp16(bs + 2*ARR + cp_off, &d_W2hT[cr*128 + cp]);
            cp16(bs + 3*ARR + cp_off, &d_W2lT[cr*128 + cp]);
            CP_COMMIT();
            CP_WAIT(1);
        } else {
            CP_WAIT(0);
        }
        __syncthreads();

        const uint32_t bs = s_base + (uint32_t)(kc & 1)*BUF;
        uint32_t ah[4][4];
#pragma unroll
        for (int mi = 0; mi < 4; mi++)
            ldm_x4(ah[mi][0], ah[mi][1], ah[mi][2], ah[mi][3],
                   bs + 0*ARR + a_off + (uint32_t)(mi*16*48));
        uint32_t bh[2][4], bl[2][4];
#pragma unroll
        for (int h = 0; h < 2; h++) {
            ldm_x4(bh[h][0], bh[h][1], bh[h][2], bh[h][3],
                   bs + 2*ARR + b_off + (uint32_t)(h*16*48));
            ldm_x4(bl[h][0], bl[h][1], bl[h][2], bl[h][3],
                   bs + 3*ARR + b_off + (uint32_t)(h*16*48));
        }
#pragma unroll
        for (int mi = 0; mi < 4; mi++) {
#pragma unroll
            for (int ni = 0; ni < 4; ni++) {
                const int h = ni >> 1, p = ni & 1;
                mma16816(acc[mi][ni], ah[mi], bh[h][p*2], bh[h][p*2+1]);
                mma16816(acc[mi][ni], ah[mi], bl[h][p*2], bl[h][p*2+1]);
            }
        }
#pragma unroll
        for (int mi = 0; mi < 4; mi++) {
            uint32_t alf[4];
            ldm_x4(alf[0], alf[1], alf[2], alf[3],
                   bs + 1*ARR + a_off + (uint32_t)(mi*16*48));
#pragma unroll
            for (int ni = 0; ni < 4; ni++) {
                const int h = ni >> 1, p = ni & 1;
                mma16816(acc[mi][ni], alf, bh[h][p*2], bh[h][p*2+1]);
            }
        }
        __syncthreads();
    }

#pragma unroll
    for (int mi = 0; mi < 4; mi++) {
#pragma unroll
        for (int ni = 0; ni < 4; ni++) {
            const int r0 = row0 + wm*64 + mi*16 + lr;
            const int colg = wn*32 + ni*8 + 2*lc;
            const float bb0 = __ldg(&tb2[colg]);
            const float bb1 = __ldg(&tb2[colg+1]);
            float2 v0, v1;
            v0.x = __expf(ftanh(acc[mi][ni][0] + bb0));
            v0.y = __expf(ftanh(acc[mi][ni][1] + bb1));
            v1.x = __expf(ftanh(acc[mi][ni][2] + bb0));
            v1.y = __expf(ftanh(acc[mi][ni][3] + bb1));
            *reinterpret_cast<float2*>(&d_g[r0*128 + colg])     = v0;
            *reinterpret_cast<float2*>(&d_g[(r0+8)*128 + colg]) = v1;
        }
    }
}

// =====================================================================
// K5: scattering chain on g (f32x2 over the m-pair), per (b,n,m-pair).
// =====================================================================
__global__ void __launch_bounds__(128) k5_scat(
    const float* __restrict__ scat, const float* __restrict__ sscat,
    const float* __restrict__ vwt,
    const float* __restrict__ sb0, const float* __restrict__ sb1,
    const float* __restrict__ out_w)
{
    __shared__ float buf[8704];      // g(17x256 pairs) | rr(17x256) at +4352
    __shared__ ull   ws2[272];
    __shared__ float sres[256];
    __shared__ float sred[8];

    const int bx   = blockIdx.x;              // 0..4095
    const int pair = bx & 31;
    const int n    = (bx >> 5) & 31;
    const int b    = bx >> 10;
    const int t    = threadIdx.x;
    const int th   = t >> 6;
    const int tc   = t & 63;
    const int kbs  = th ? 9 : 0;
    const int kcs  = th ? 8 : 9;

    for (int i = t; i < 272; i += 128) {
        const int row = i >> 4, j = i & 15;
        float v = (row == 0) ? (1.0f - scat[(b*Nn+n)*Kk + j])
                             : (1.0f - sscat[b*256 + (row-1)*Kk + j]);
        v *= vwt[b*Kk + j];
        ws2[i] = pack2(v, v);
    }

    const int bnm0 = ((b*Nn + n)*Mm + pair*2);
#pragma unroll
    for (int k = 0; k < K1; k++) {
        const float g0 = d_g[(bnm0*K1 + k)*128 + t];
        const float g1 = d_g[((bnm0+1)*K1 + k)*128 + t];
        *reinterpret_cast<ull*>(buf + k*256 + 2*t) = pack2(g0, g1);
    }
    __syncthreads();

    const float sb0a = sb0[tc], sb0b = sb0[tc+64];
    const float sb1c = sb1[t];
    const float owc  = out_w[t];

    // ---- stage 1: rr[k] = sum_j ws2[k][j]*g[1+j] ----
    {
        ull g2r[Kk];
#pragma unroll
        for (int j = 0; j < Kk; j++)
            g2r[j] = *reinterpret_cast<const ull*>(buf + (1+j)*256 + 2*t);
#pragma unroll
        for (int k = 0; k < K1; k++) {
            ull r = 0ull;
            const ulonglong2* wsp = reinterpret_cast<const ulonglong2*>(ws2 + k*Kk);
#pragma unroll
            for (int jp = 0; jp < 8; jp++) {
                const ulonglong2 wv = wsp[jp];
                fma2(r, g2r[2*jp],   wv.x);
                fma2(r, g2r[2*jp+1], wv.y);
            }
            *reinterpret_cast<ull*>(buf + 4352 + k*256 + 2*t) = r;
        }
        __syncthreads();
    }

    // ---- stage 2: g[k][c] += tanh(sw0T[:,c]@rr[k][:] + sb0[c]); k-split, 2 cols ----
    {
        ull sA[9], sB[9];
#pragma unroll
        for (int k = 0; k < 9; k++) { sA[k] = 0ull; sB[k] = 0ull; }
        const float* wb = d_sw0T + tc;
        float wcA[4], wcB[4], wnA[4], wnB[4];
#pragma unroll
        for (int ww = 0; ww < 4; ww++) { wcA[ww] = wb[ww*Ww]; wcB[ww] = wb[ww*Ww + 64]; }
#pragma unroll 1
        for (int w = 0; w < Ww; w += 4) {
            if (w + 4 < Ww) {
                const float* wp = wb + (w+4)*Ww;
#pragma unroll
                for (int ww = 0; ww < 4; ww++) { wnA[ww] = wp[ww*Ww]; wnB[ww] = wp[ww*Ww + 64]; }
            }
            const ull pA0 = pack2(wcA[0],wcA[0]), pA1 = pack2(wcA[1],wcA[1]),
                      pA2 = pack2(wcA[2],wcA[2]), pA3 = pack2(wcA[3],wcA[3]);
            const ull pB0 = pack2(wcB[0],wcB[0]), pB1 = pack2(wcB[1],wcB[1]),
                      pB2 = pack2(wcB[2],wcB[2]), pB3 = pack2(wcB[3],wcB[3]);
#pragma unroll
            for (int k = 0; k < 9; k++) {
                if (k < kcs) {
                    ulonglong2 ra = *reinterpret_cast<const ulonglong2*>(buf + 4352 + (kbs+k)*256 + w*2);
                    ulonglong2 rb = *reinterpret_cast<const ulonglong2*>(buf + 4352 + (kbs+k)*256 + w*2 + 4);
                    fma2(sA[k], ra.x, pA0); fma2(sA[k], ra.y, pA1);
                    fma2(sA[k], rb.x, pA2); fma2(sA[k], rb.y, pA3);
                    fma2(sB[k], ra.x, pB0); fma2(sB[k], ra.y, pB1);
                    fma2(sB[k], rb.x, pB2); fma2(sB[k], rb.y, pB3);
                }
            }
#pragma unroll
            for (int q = 0; q < 4; q++) { wcA[q] = wnA[q]; wcB[q] = wnB[q]; }
        }
#pragma unroll
        for (int k = 0; k < 9; k++) {
            if (k < kcs) {
                float a0, a1; unpack2(sA[k], a0, a1);
                ull* gp = reinterpret_cast<ull*>(buf + (kbs+k)*256 + 2*tc);
                float g0, g1; unpack2(*gp, g0, g1);
                *gp = pack2(g0 + ftanh(a0+sb0a), g1 + ftanh(a1+sb0a));
                unpack2(sB[k], a0, a1);
                gp = reinterpret_cast<ull*>(buf + (kbs+k)*256 + 2*(tc+64));
                unpack2(*gp, g0, g1);
                *gp = pack2(g0 + ftanh(a0+sb0b), g1 + ftanh(a1+sb0b));
            }
        }
        __syncthreads();
    }

    // ---- stage 3 ----
    {
        ull rv = 0ull;
#pragma unroll
        for (int k = 0; k < Kk; k++)
            fma2(rv, *reinterpret_cast<const ull*>(buf + (1+k)*256 + 2*t), ws2[k]);
        *reinterpret_cast<ull*>(sres + 2*t) = rv;
    }
    __syncthreads();

    // ---- stage 4 ----
    {
        ull sa = 0ull, sb = 0ull;
        const float* wb = d_sw1T + t;
#pragma unroll 1
        for (int w = 0; w < Ww; w += 4) {
            const float v0w = wb[(w+0)*Ww];
            const float v1w = wb[(w+1)*Ww];
            const float v2w = wb[(w+2)*Ww];
            const float v3w = wb[(w+3)*Ww];
            ulonglong2 ra = *reinterpret_cast<const ulonglong2*>(sres + w*2);
            ulonglong2 rb = *reinterpret_cast<const ulonglong2*>(sres + w*2 + 4);
            fma2(sa, ra.x, pack2(v0w,v0w)); fma2(sb, ra.y, pack2(v1w,v1w));
            fma2(sa, rb.x, pack2(v2w,v2w)); fma2(sb, rb.y, pack2(v3w,v3w));
        }
        const ull tot = add2(sa, sb);
        float a0, a1; unpack2(tot, a0, a1);
        float v0, v1; unpack2(*reinterpret_cast<const ull*>(buf + 2*t), v0, v1);
        float p0 = (v0 + ftanh(a0+sb1c)) * owc;
        float p1 = (v1 + ftanh(a1+sb1c)) * owc;
#pragma unroll
        for (int o = 16; o > 0; o >>= 1) {
            p0 += __shfl_down_sync(0xffffffffu, p0, o);
            p1 += __shfl_down_sync(0xffffffffu, p1, o);
        }
        if ((t & 31) == 0) { sred[(t>>5)*2] = p0; sred[(t>>5)*2+1] = p1; }
        __syncthreads();
        if (t == 0) {
            d_gdot[(b*Nn+n)*Mm + pair*2 + 0] = sred[0]+sred[2]+sred[4]+sred[6];
            d_gdot[(b*Nn+n)*Mm + pair*2 + 1] = sred[1]+sred[3]+sred[5]+sred[7];
        }
    }
}

// =====================================================================
__global__ void k6_final(const float* __restrict__ boundary,
                         const float* __restrict__ bweights,
                         float* __restrict__ out)
{
    __shared__ float s2[2];
    const int bn = blockIdx.x;
    const int b  = bn >> 5;
    const int t  = threadIdx.x;
    float v = d_gdot[bn*Mm + t] * boundary[b*Mm + t] * bweights[b*Mm + t];
#pragma unroll
    for (int o = 16; o > 0; o >>= 1) v += __shfl_down_sync(0xffffffffu, v, o);
    if ((t & 31) == 0) s2[t >> 5] = v;
    __syncthreads();
    if (t == 0) out[bn] = s2[0] + s2[1];
}

// =====================================================================
extern "C" void kernel_launch(void* const* d_in, const int* in_sizes, int n_in,
                              void* d_out, int out_size)
{
    const float* phase    = (const float*)d_in[0];
    const float* bcoords  = (const float*)d_in[1];
    const float* boundary = (const float*)d_in[2];
    const float* bweights = (const float*)d_in[3];
    const float* posc     = (const float*)d_in[4];
    const float* sigma    = (const float*)d_in[5];
    const float* velc     = (const float*)d_in[6];
    const float* vwt      = (const float*)d_in[7];
    const float* scat     = (const float*)d_in[8];
    const float* sscat    = (const float*)d_in[9];
    const float* aw0 = (const float*)d_in[10];
    const float* ab0 = (const float*)d_in[11];
    const float* aw1 = (const float*)d_in[12];
    const float* ab1 = (const float*)d_in[13];
    const float* aw2 = (const float*)d_in[14];
    const float* ab2 = (const float*)d_in[15];
    const float* tw0 = (const float*)d_in[16];
    const float* tb0 = (const float*)d_in[17];
    const float* tw1 = (const float*)d_in[18];
    const float* tb1 = (const float*)d_in[19];
    const float* tw2 = (const float*)d_in[20];
    const float* tb2 = (const float*)d_in[21];
    const float* sw0 = (const float*)d_in[22];
    const float* sb0 = (const float*)d_in[23];
    const float* sw1 = (const float*)d_in[24];
    const float* sb1 = (const float*)d_in[25];
    const float* ow  = (const float*)d_in[26];
    float* out = (float*)d_out;

    k_prep<<<128, 256>>>(tw1, tw2, sw0, sw1);
    k1_attn<<<Bb*Nn*K1, 128>>>(phase, posc, sigma, velc,
                               aw0, ab0, aw1, ab1, aw2, ab2, tw0, tb0);
    k_bm<<<Bb*Mm, TWd>>>(bcoords, tw0);
    k_h0<<<Bb*Nn*Mm, 128>>>();
    k_g1<<<NTILES, 256>>>(tb1);
    k_g2<<<NTILES, 256>>>(tb2);
    k5_scat<<<Bb*Nn*(Mm/2), 128>>>(scat, sscat, vwt, sb0, sb1, ow);
    k6_final<<<Bb*Nn, 64>>>(boundary, bweights, out);
}

// round 16
// speedup vs baseline: 1.5567x; 1.0016x over previous
#include <cuda_runtime.h>
#include <cuda_bf16.h>
#include <math.h>
#include <cstdint>

#define Bb 4
#define Nn 32
#define Mm 64
#define Kk 16
#define K1 17
#define Pp 128
#define Ww 128
#define TWd 256
#define NROWS (Bb*Nn*Mm*K1)      /* 139264 */
#define NTILES (NROWS/128)       /* 1088 */

typedef unsigned long long ull;

// ---------- f32x2 helpers ----------
__device__ __forceinline__ ull pack2(float a, float b) {
    ull r; asm("mov.b64 %0, {%1, %2};" : "=l"(r) : "f"(a), "f"(b)); return r;
}
__device__ __forceinline__ void unpack2(ull v, float& a, float& b) {
    asm("mov.b64 {%0, %1}, %2;" : "=f"(a), "=f"(b) : "l"(v));
}
__device__ __forceinline__ void fma2(ull& d, ull a, ull b) {
    asm("fma.rn.f32x2 %0, %1, %2, %0;" : "+l"(d) : "l"(a), "l"(b));
}
__device__ __forceinline__ ull add2(ull a, ull b) {
    ull r; asm("add.rn.f32x2 %0, %1, %2;" : "=l"(r) : "l"(a), "l"(b)); return r;
}
__device__ __forceinline__ float ftanh(float x) {
    float e = __expf(2.0f * x);
    return 1.0f - __fdividef(2.0f, e + 1.0f);
}
// bf16 split helpers
__device__ __forceinline__ unsigned short bfh(float x) {
    __nv_bfloat16 h = __float2bfloat16(x);
    return *reinterpret_cast<unsigned short*>(&h);
}
__device__ __forceinline__ unsigned short bfl(float x) {
    __nv_bfloat16 h = __float2bfloat16(x);
    float r = x - __bfloat162float(h);
    __nv_bfloat16 l = __float2bfloat16(r);
    return *reinterpret_cast<unsigned short*>(&l);
}
__device__ __forceinline__ unsigned packhi2(float a, float b) {
    return (unsigned)bfh(a) | ((unsigned)bfh(b) << 16);
}
__device__ __forceinline__ unsigned packlo2(float a, float b) {
    return (unsigned)bfl(a) | ((unsigned)bfl(b) << 16);
}
__device__ __forceinline__ uint32_t smem_to_u32(const void* p) {
    uint32_t a;
    asm("{ .reg .u64 tmp; cvta.to.shared.u64 tmp, %1; cvt.u32.u64 %0, tmp; }" : "=r"(a) : "l"(p));
    return a;
}
__device__ __forceinline__ void ldm_x4(uint32_t& r0, uint32_t& r1, uint32_t& r2, uint32_t& r3, uint32_t addr) {
    asm volatile("ldmatrix.sync.aligned.m8n8.x4.shared.b16 {%0,%1,%2,%3}, [%4];"
                 : "=r"(r0), "=r"(r1), "=r"(r2), "=r"(r3) : "r"(addr));
}
__device__ __forceinline__ void mma16816(float* c, const uint32_t* a, uint32_t b0, uint32_t b1) {
    asm volatile("mma.sync.aligned.m16n8k16.row.col.f32.bf16.bf16.f32 "
                 "{%0,%1,%2,%3}, {%4,%5,%6,%7}, {%8,%9}, {%0,%1,%2,%3};"
                 : "+f"(c[0]), "+f"(c[1]), "+f"(c[2]), "+f"(c[3])
                 : "r"(a[0]), "r"(a[1]), "r"(a[2]), "r"(a[3]), "r"(b0), "r"(b1));
}
__device__ __forceinline__ void cp16(uint32_t saddr, const void* gaddr) {
    asm volatile("cp.async.cg.shared.global [%0], [%1], 16;" :: "r"(saddr), "l"(gaddr));
}
#define CP_COMMIT() asm volatile("cp.async.commit_group;" ::: "memory")
#define CP_WAIT(n)  asm volatile("cp.async.wait_group %0;" :: "n"(n) : "memory")

// ------- scratch (device globals; no runtime allocation) -------
__device__ float d_A[Bb*Nn*K1*TWd];
__device__ float d_Bm[Bb*Mm*TWd];
__device__ float d_gdot[Bb*Nn*Mm];
__device__ float d_sw0T[Ww*Ww];             // [w][i]
__device__ float d_sw1T[Ww*Ww];             // [w][i]
__device__ unsigned d_W1hT[256*128];        // [n][kpair] bf16x2 (hi)
__device__ unsigned d_W1lT[256*128];        // (lo)
__device__ unsigned d_W2hT[128*128];
__device__ unsigned d_W2lT[128*128];
__device__ unsigned d_H0h[NROWS*128];
__device__ unsigned d_H0l[NROWS*128];
__device__ unsigned d_H1h[NROWS*128];
__device__ unsigned d_H1l[NROWS*128];
__device__ float    d_g [NROWS*128];

// =====================================================================
// K_prep: split-transposed weights + sw transposes
// =====================================================================
__global__ void k_prep(const float* __restrict__ tw1, const float* __restrict__ tw2,
                       const float* __restrict__ sw0, const float* __restrict__ sw1)
{
    const int idx = blockIdx.x*256 + threadIdx.x;   // 0..32767
    {
        const int n = idx >> 7, kp = idx & 127;
        const float w0 = tw1[(2*kp)*256 + n];
        const float w1 = tw1[(2*kp+1)*256 + n];
        d_W1hT[n*128 + kp] = packhi2(w0, w1);
        d_W1lT[n*128 + kp] = packlo2(w0, w1);
    }
    if (idx < 16384) {
        const int n = idx >> 7, kp = idx & 127;
        const float w0 = tw2[(2*kp)*128 + n];
        const float w1 = tw2[(2*kp+1)*128 + n];
        d_W2hT[n*128 + kp] = packhi2(w0, w1);
        d_W2lT[n*128 + kp] = packlo2(w0, w1);
        const int i = idx >> 7, w = idx & 127;
        d_sw0T[w*Ww + i] = sw0[idx];
        d_sw1T[w*Ww + i] = sw1[idx];
    }
}

// =====================================================================
// K1: attention MLP + softmax + coeff + A-partial.  One block per (b,n,k1).
// =====================================================================
__global__ void __launch_bounds__(128) k1_attn(
    const float* __restrict__ phase, const float* __restrict__ posc,
    const float* __restrict__ sigma, const float* __restrict__ velc,
    const float* __restrict__ aw0, const float* __restrict__ ab0,
    const float* __restrict__ aw1, const float* __restrict__ ab1,
    const float* __restrict__ aw2, const float* __restrict__ ab2,
    const float* __restrict__ tw0, const float* __restrict__ tb0)
{
    __shared__ float s_aw0[6*64];
    __shared__ float s_ab0[64];
    __shared__ float s_aw1[64*64];
    __shared__ float s_ab1[64];
    __shared__ float s_aw2[64];
    __shared__ float red[128];

    const int bx = blockIdx.x;
    const int k1 = bx % K1;
    const int n  = (bx / K1) % Nn;
    const int b  = bx / (K1*Nn);
    const int t  = threadIdx.x;

    for (int i = t; i < 6*64; i += 128) s_aw0[i] = aw0[i];
    if (t < 64) { s_ab0[t] = ab0[t]; s_aw2[t] = aw2[t]; s_ab1[t] = ab1[t]; }
    for (int i = t; i < 64*64; i += 128) s_aw1[i] = aw1[i];
    __syncthreads();

    const float x0 = phase[(b*Nn+n)*4 + 0];
    const float x1 = phase[(b*Nn+n)*4 + 1];
    float va0, va1;
    if (k1 == 0) { va0 = phase[(b*Nn+n)*4 + 2]; va1 = phase[(b*Nn+n)*4 + 3]; }
    else         { va0 = velc[(b*Kk + (k1-1))*2 + 0]; va1 = velc[(b*Kk + (k1-1))*2 + 1]; }
    const float inv = rsqrtf(va0*va0 + va1*va1 + 1e-16f);
    const float ag0 = va0*inv, ag1 = va1*inv;

    const float rx = x0 - posc[(b*Pp + t)*2 + 0];
    const float ry = x1 - posc[(b*Pp + t)*2 + 1];
    const float rd = sqrtf(rx*rx + ry*ry + 1e-16f);
    const float pl = rx*ag0 + ry*ag1;
    const float al = pl / (rd + 1e-8f);

    float h0[64];
#pragma unroll
    for (int j = 0; j < 64; j++) {
        h0[j] = ftanh(s_ab0[j] + x0*s_aw0[0*64+j] + x1*s_aw0[1*64+j]
                              + va0*s_aw0[2*64+j] + va1*s_aw0[3*64+j]
                              + al*s_aw0[4*64+j] + pl*s_aw0[5*64+j]);
    }
    float logit = ab2[0];
#pragma unroll
    for (int g = 0; g < 4; g++) {
        ull acc[8];
#pragma unroll
        for (int p = 0; p < 8; p++) acc[p] = 0ull;
        for (int j = 0; j < 64; j++) {
            const ull hp = pack2(h0[j], h0[j]);
            const float* wrow = &s_aw1[j*64 + g*16];
            ulonglong2 wA = *reinterpret_cast<const ulonglong2*>(wrow + 0);
            ulonglong2 wB = *reinterpret_cast<const ulonglong2*>(wrow + 4);
            ulonglong2 wC = *reinterpret_cast<const ulonglong2*>(wrow + 8);
            ulonglong2 wD = *reinterpret_cast<const ulonglong2*>(wrow + 12);
            fma2(acc[0], hp, wA.x); fma2(acc[1], hp, wA.y);
            fma2(acc[2], hp, wB.x); fma2(acc[3], hp, wB.y);
            fma2(acc[4], hp, wC.x); fma2(acc[5], hp, wC.y);
            fma2(acc[6], hp, wD.x); fma2(acc[7], hp, wD.y);
        }
#pragma unroll
        for (int p = 0; p < 8; p++) {
            const int i = g*16 + p*2;
            float a0, a1; unpack2(acc[p], a0, a1);
            logit += ftanh(a0 + s_ab1[i])   * s_aw2[i]
                   + ftanh(a1 + s_ab1[i+1]) * s_aw2[i+1];
        }
    }

    float lg = (pl > 0.0f) ? logit : -1e30f;
    red[t] = lg; __syncthreads();
    for (int s = 64; s > 0; s >>= 1) { if (t < s) red[t] = fmaxf(red[t], red[t+s]); __syncthreads(); }
    const float mx = red[0]; __syncthreads();
    const float e = __expf(lg - mx);
    red[t] = e; __syncthreads();
    for (int s = 64; s > 0; s >>= 1) { if (t < s) red[t] += red[t+s]; __syncthreads(); }
    const float denom = red[0]; __syncthreads();
    const float aw = e / denom;

    const float sg0 = sigma[(b*Pp+t)*2 + 0];
    const float sg1 = sigma[(b*Pp+t)*2 + 1];
    red[t] = aw*sg0; __syncthreads();
    for (int s = 64; s > 0; s >>= 1) { if (t < s) red[t] += red[t+s]; __syncthreads(); }
    const float sum0 = red[0]; __syncthreads();
    red[t] = aw*sg1; __syncthreads();
    for (int s = 64; s > 0; s >>= 1) { if (t < s) red[t] += red[t+s]; __syncthreads(); }
    const float sum1 = red[0]; __syncthreads();

    const float c0 = __expf(-sum0);
    const float c1 = __expf(-sum1);

    for (int tt = t; tt < TWd; tt += 128) {
        float a = tb0[tt]
                + x0*tw0[0*TWd+tt] + x1*tw0[1*TWd+tt]
                + va0*tw0[2*TWd+tt] + va1*tw0[3*TWd+tt]
                + c0*tw0[8*TWd+tt] + c1*tw0[9*TWd+tt];
        d_A[bx*TWd + tt] = a;
    }
}

// =====================================================================
__global__ void k_bm(const float* __restrict__ bcoords, const float* __restrict__ tw0)
{
    const int bm = blockIdx.x;
    const int t  = threadIdx.x;
    const float xp0 = bcoords[bm*4+0], xp1 = bcoords[bm*4+1];
    const float vp0 = bcoords[bm*4+2], vp1 = bcoords[bm*4+3];
    d_Bm[bm*TWd + t] = xp0*tw0[4*TWd+t] + xp1*tw0[5*TWd+t]
                     + vp0*tw0[6*TWd+t] + vp1*tw0[7*TWd+t];
}

// =====================================================================
// K_h0: H0 = tanh(A + Bm) as bf16-split pair arrays.  Block per (b,n,m).
// =====================================================================
__global__ void __launch_bounds__(128) k_h0()
{
    const int bnm = blockIdx.x;            // 0..8191
    const int m   = bnm & 63;
    const int bn  = bnm >> 6;              // b*32+n
    const int t   = threadIdx.x;           // pair index 0..127
    const float* Arow = d_A + bn*K1*TWd;
    const float* Bm   = d_Bm + ((bn >> 5)*Mm + m)*TWd;
    const float bm0 = Bm[2*t], bm1 = Bm[2*t+1];
#pragma unroll
    for (int k = 0; k < K1; k++) {
        const float v0 = ftanh(Arow[k*TWd + 2*t]     + bm0);
        const float v1 = ftanh(Arow[k*TWd + 2*t + 1] + bm1);
        const int o = (bnm*K1 + k)*128 + t;
        d_H0h[o] = packhi2(v0, v1);
        d_H0l[o] = packlo2(v0, v1);
    }
}

// =====================================================================
// K_g1: H1 = tanh(H0 @ tw1 + tb1).  cp.async double-buffered stages.
// MMA issue reordered into 3 independent sweeps (no acc RAW chains).
// =====================================================================
__global__ void __launch_bounds__(256, 2) k_g1(const float* __restrict__ tb1)
{
    __shared__ unsigned stage[2][4][128*12];

    const int t   = threadIdx.x;
    const int lid = t & 31, wid = t >> 5;
    const int wm  = wid >> 2, wn = wid & 3;
    const int row0 = blockIdx.x * 128;
    const int lr = lid >> 2, lc = lid & 3;

    const int cr = t >> 1, cj4 = t & 1;
    const uint32_t s_base = smem_to_u32(stage);
    const uint32_t cp_off = (uint32_t)((cr*12 + cj4*4)*4);

    const int arow  = wm*64 + (lid & 7) + ((lid >> 3) & 1)*8;
    const uint32_t a_off = (uint32_t)(arow*48 + ((lid >> 4)*8)*2);
    const int brow  = wn*32 + ((lid >> 4)*8) + (lid & 7);
    const uint32_t b_off = (uint32_t)(brow*48 + (((lid >> 3) & 1)*8)*2);
    const uint32_t BUF = 4u*128u*12u*4u;   // bytes per buffer
    const uint32_t ARR = 128u*12u*4u;      // bytes per array

    for (int pass = 0; pass < 2; pass++) {
        float acc[4][4][4];
#pragma unroll
        for (int mi = 0; mi < 4; mi++)
#pragma unroll
            for (int ni = 0; ni < 4; ni++)
#pragma unroll
                for (int e = 0; e < 4; e++) acc[mi][ni][e] = 0.0f;

        // prologue: prefetch chunk 0 into buf 0
        {
            const int cp = 0*8 + cj4*4;
            cp16(s_base + 0*BUF + 0*ARR + cp_off, &d_H0h[(row0 + cr)*128 + cp]);
            cp16(s_base + 0*BUF + 1*ARR + cp_off, &d_H0l[(row0 + cr)*128 + cp]);
            cp16(s_base + 0*BUF + 2*ARR + cp_off, &d_W1hT[(pass*128 + cr)*128 + cp]);
            cp16(s_base + 0*BUF + 3*ARR + cp_off, &d_W1lT[(pass*128 + cr)*128 + cp]);
            CP_COMMIT();
        }

#pragma unroll 1
        for (int kc = 0; kc < 16; kc++) {
            if (kc + 1 < 16) {
                const uint32_t bs = s_base + (uint32_t)((kc+1) & 1)*BUF;
                const int cp = (kc+1)*8 + cj4*4;
                cp16(bs + 0*ARR + cp_off, &d_H0h[(row0 + cr)*128 + cp]);
                cp16(bs + 1*ARR + cp_off, &d_H0l[(row0 + cr)*128 + cp]);
                cp16(bs + 2*ARR + cp_off, &d_W1hT[(pass*128 + cr)*128 + cp]);
                cp16(bs + 3*ARR + cp_off, &d_W1lT[(pass*128 + cr)*128 + cp]);
                CP_COMMIT();
                CP_WAIT(1);
            } else {
                CP_WAIT(0);
            }
            __syncthreads();

            const uint32_t bs = s_base + (uint32_t)(kc & 1)*BUF;
            uint32_t ah[4][4];
#pragma unroll
            for (int mi = 0; mi < 4; mi++)
                ldm_x4(ah[mi][0], ah[mi][1], ah[mi][2], ah[mi][3],
                       bs + 0*ARR + a_off + (uint32_t)(mi*16*48));
            uint32_t bh[2][4], bl[2][4];
#pragma unroll
            for (int h = 0; h < 2; h++) {
                ldm_x4(bh[h][0], bh[h][1], bh[h][2], bh[h][3],
                       bs + 2*ARR + b_off + (uint32_t)(h*16*48));
                ldm_x4(bl[h][0], bl[h][1], bl[h][2], bl[h][3],
                       bs + 3*ARR + b_off + (uint32_t)(h*16*48));
            }
            // sweep 1: hi*hi  (16 independent MMAs)
#pragma unroll
            for (int mi = 0; mi < 4; mi++)
#pragma unroll
                for (int ni = 0; ni < 4; ni++) {
                    const int h = ni >> 1, p = ni & 1;
                    mma16816(acc[mi][ni], ah[mi], bh[h][p*2], bh[h][p*2+1]);
                }
            // sweep 2: hi*lo  (16 independent; reuse distance 16)
#pragma unroll
            for (int mi = 0; mi < 4; mi++)
#pragma unroll
                for (int ni = 0; ni < 4; ni++) {
                    const int h = ni >> 1, p = ni & 1;
                    mma16816(acc[mi][ni], ah[mi], bl[h][p*2], bl[h][p*2+1]);
                }
            // sweep 3: lo*hi
#pragma unroll
            for (int mi = 0; mi < 4; mi++) {
                uint32_t alf[4];
                ldm_x4(alf[0], alf[1], alf[2], alf[3],
                       bs + 1*ARR + a_off + (uint32_t)(mi*16*48));
#pragma unroll
                for (int ni = 0; ni < 4; ni++) {
                    const int h = ni >> 1, p = ni & 1;
                    mma16816(acc[mi][ni], alf, bh[h][p*2], bh[h][p*2+1]);
                }
            }
            __syncthreads();
        }

        // epilogue: tanh + bf16-split pack
#pragma unroll
        for (int mi = 0; mi < 4; mi++) {
#pragma unroll
            for (int ni = 0; ni < 4; ni++) {
                const int r0 = row0 + wm*64 + mi*16 + lr;
                const int colg = pass*128 + wn*32 + ni*8 + 2*lc;
                const float bb0 = __ldg(&tb1[colg]);
                const float bb1 = __ldg(&tb1[colg+1]);
                const float t0 = ftanh(acc[mi][ni][0] + bb0);
                const float t1 = ftanh(acc[mi][ni][1] + bb1);
                const float t2 = ftanh(acc[mi][ni][2] + bb0);
                const float t3 = ftanh(acc[mi][ni][3] + bb1);
                const int cp = colg >> 1;
                d_H1h[r0*128 + cp]     = packhi2(t0, t1);
                d_H1l[r0*128 + cp]     = packlo2(t0, t1);
                d_H1h[(r0+8)*128 + cp] = packhi2(t2, t3);
                d_H1l[(r0+8)*128 + cp] = packlo2(t2, t3);
            }
        }
        __syncthreads();
    }
}

// =====================================================================
// K_g2: g = exp(tanh(H1 @ tw2 + tb2)).  Same pipeline + sweep reorder.
// =====================================================================
__global__ void __launch_bounds__(256, 2) k_g2(const float* __restrict__ tb2)
{
    __shared__ unsigned stage[2][4][128*12];

    const int t   = threadIdx.x;
    const int lid = t & 31, wid = t >> 5;
    const int wm  = wid >> 2, wn = wid & 3;
    const int row0 = blockIdx.x * 128;
    const int lr = lid >> 2, lc = lid & 3;

    const int cr = t >> 1, cj4 = t & 1;
    const uint32_t s_base = smem_to_u32(stage);
    const uint32_t cp_off = (uint32_t)((cr*12 + cj4*4)*4);

    const int arow  = wm*64 + (lid & 7) + ((lid >> 3) & 1)*8;
    const uint32_t a_off = (uint32_t)(arow*48 + ((lid >> 4)*8)*2);
    const int brow  = wn*32 + ((lid >> 4)*8) + (lid & 7);
    const uint32_t b_off = (uint32_t)(brow*48 + (((lid >> 3) & 1)*8)*2);
    const uint32_t BUF = 4u*128u*12u*4u;
    const uint32_t ARR = 128u*12u*4u;

    float acc[4][4][4];
#pragma unroll
    for (int mi = 0; mi < 4; mi++)
#pragma unroll
        for (int ni = 0; ni < 4; ni++)
#pragma unroll
            for (int e = 0; e < 4; e++) acc[mi][ni][e] = 0.0f;

    {
        const int cp = cj4*4;
        cp16(s_base + 0*BUF + 0*ARR + cp_off, &d_H1h[(row0 + cr)*128 + cp]);
        cp16(s_base + 0*BUF + 1*ARR + cp_off, &d_H1l[(row0 + cr)*128 + cp]);
        cp16(s_base + 0*BUF + 2*ARR + cp_off, &d_W2hT[cr*128 + cp]);
        cp16(s_base + 0*BUF + 3*ARR + cp_off, &d_W2lT[cr*128 + cp]);
        CP_COMMIT();
    }

#pragma unroll 1
    for (int kc = 0; kc < 16; kc++) {
        if (kc + 1 < 16) {
            const uint32_t bs = s_base + (uint32_t)((kc+1) & 1)*BUF;
            const int cp = (kc+1)*8 + cj4*4;
            cp16(bs + 0*ARR + cp_off, &d_H1h[(row0 + cr)*128 + cp]);
            cp16(bs + 1*ARR + cp_off, &d_H1l[(row0 + cr)*128 + cp]);
            cp16(bs + 2*ARR + cp_off, &d_W2hT[cr*128 + cp]);
            cp16(bs + 3*ARR + cp_off, &d_W2lT[cr*128 + cp]);
            CP_COMMIT();
            CP_WAIT(1);
        } else {
            CP_WAIT(0);
        }
        __syncthreads();

        const uint32_t bs = s_base + (uint32_t)(kc & 1)*BUF;
        uint32_t ah[4][4];
#pragma unroll
        for (int mi = 0; mi < 4; mi++)
            ldm_x4(ah[mi][0], ah[mi][1], ah[mi][2], ah[mi][3],
                   bs + 0*ARR + a_off + (uint32_t)(mi*16*48));
        uint32_t bh[2][4], bl[2][4];
#pragma unroll
        for (int h = 0; h < 2; h++) {
            ldm_x4(bh[h][0], bh[h][1], bh[h][2], bh[h][3],
                   bs + 2*ARR + b_off + (uint32_t)(h*16*48));
            ldm_x4(bl[h][0], bl[h][1], bl[h][2], bl[h][3],
                   bs + 3*ARR + b_off + (uint32_t)(h*16*48));
        }
#pragma unroll
        for (int mi = 0; mi < 4; mi++)
#pragma unroll
            for (int ni = 0; ni < 4; ni++) {
                const int h = ni >> 1, p = ni & 1;
                mma16816(acc[mi][ni], ah[mi], bh[h][p*2], bh[h][p*2+1]);
            }
#pragma unroll
        for (int mi = 0; mi < 4; mi++)
#pragma unroll
            for (int ni = 0; ni < 4; ni++) {
                const int h = ni >> 1, p = ni & 1;
                mma16816(acc[mi][ni], ah[mi], bl[h][p*2], bl[h][p*2+1]);
            }
#pragma unroll
        for (int mi = 0; mi < 4; mi++) {
            uint32_t alf[4];
            ldm_x4(alf[0], alf[1], alf[2], alf[3],
                   bs + 1*ARR + a_off + (uint32_t)(mi*16*48));
#pragma unroll
            for (int ni = 0; ni < 4; ni++) {
                const int h = ni >> 1, p = ni & 1;
                mma16816(acc[mi][ni], alf, bh[h][p*2], bh[h][p*2+1]);
            }
        }
        __syncthreads();
    }

#pragma unroll
    for (int mi = 0; mi < 4; mi++) {
#pragma unroll
        for (int ni = 0; ni < 4; ni++) {
            const int r0 = row0 + wm*64 + mi*16 + lr;
            const int colg = wn*32 + ni*8 + 2*lc;
            const float bb0 = __ldg(&tb2[colg]);
            const float bb1 = __ldg(&tb2[colg+1]);
            float2 v0, v1;
            v0.x = __expf(ftanh(acc[mi][ni][0] + bb0));
            v0.y = __expf(ftanh(acc[mi][ni][1] + bb1));
            v1.x = __expf(ftanh(acc[mi][ni][2] + bb0));
            v1.y = __expf(ftanh(acc[mi][ni][3] + bb1));
            *reinterpret_cast<float2*>(&d_g[r0*128 + colg])     = v0;
            *reinterpret_cast<float2*>(&d_g[(r0+8)*128 + colg]) = v1;
        }
    }
}

// =====================================================================
// K5: scattering chain on g (f32x2 over the m-pair), per (b,n,m-pair).
// =====================================================================
__global__ void __launch_bounds__(128) k5_scat(
    const float* __restrict__ scat, const float* __restrict__ sscat,
    const float* __restrict__ vwt,
    const float* __restrict__ sb0, const float* __restrict__ sb1,
    const float* __restrict__ out_w)
{
    __shared__ float buf[8704];      // g(17x256 pairs) | rr(17x256) at +4352
    __shared__ ull   ws2[272];
    __shared__ float sres[256];
    __shared__ float sred[8];

    const int bx   = blockIdx.x;              // 0..4095
    const int pair = bx & 31;
    const int n    = (bx >> 5) & 31;
    const int b    = bx >> 10;
    const int t    = threadIdx.x;
    const int th   = t >> 6;
    const int tc   = t & 63;
    const int kbs  = th ? 9 : 0;
    const int kcs  = th ? 8 : 9;

    for (int i = t; i < 272; i += 128) {
        const int row = i >> 4, j = i & 15;
        float v = (row == 0) ? (1.0f - scat[(b*Nn+n)*Kk + j])
                             : (1.0f - sscat[b*256 + (row-1)*Kk + j]);
        v *= vwt[b*Kk + j];
        ws2[i] = pack2(v, v);
    }

    const int bnm0 = ((b*Nn + n)*Mm + pair*2);
#pragma unroll
    for (int k = 0; k < K1; k++) {
        const float g0 = d_g[(bnm0*K1 + k)*128 + t];
        const float g1 = d_g[((bnm0+1)*K1 + k)*128 + t];
        *reinterpret_cast<ull*>(buf + k*256 + 2*t) = pack2(g0, g1);
    }
    __syncthreads();

    const float sb0a = sb0[tc], sb0b = sb0[tc+64];
    const float sb1c = sb1[t];
    const float owc  = out_w[t];

    // ---- stage 1: rr[k] = sum_j ws2[k][j]*g[1+j] ----
    {
        ull g2r[Kk];
#pragma unroll
        for (int j = 0; j < Kk; j++)
            g2r[j] = *reinterpret_cast<const ull*>(buf + (1+j)*256 + 2*t);
#pragma unroll
        for (int k = 0; k < K1; k++) {
            ull r = 0ull;
            const ulonglong2* wsp = reinterpret_cast<const ulonglong2*>(ws2 + k*Kk);
#pragma unroll
            for (int jp = 0; jp < 8; jp++) {
                const ulonglong2 wv = wsp[jp];
                fma2(r, g2r[2*jp],   wv.x);
                fma2(r, g2r[2*jp+1], wv.y);
            }
            *reinterpret_cast<ull*>(buf + 4352 + k*256 + 2*t) = r;
        }
        __syncthreads();
    }

    // ---- stage 2: g[k][c] += tanh(sw0T[:,c]@rr[k][:] + sb0[c]); k-split, 2 cols ----
    {
        ull sA[9], sB[9];
#pragma unroll
        for (int k = 0; k < 9; k++) { sA[k] = 0ull; sB[k] = 0ull; }
        const float* wb = d_sw0T + tc;
        float wcA[4], wcB[4], wnA[4], wnB[4];
#pragma unroll
        for (int ww = 0; ww < 4; ww++) { wcA[ww] = wb[ww*Ww]; wcB[ww] = wb[ww*Ww + 64]; }
#pragma unroll 1
        for (int w = 0; w < Ww; w += 4) {
            if (w + 4 < Ww) {
                const float* wp = wb + (w+4)*Ww;
#pragma unroll
                for (int ww = 0; ww < 4; ww++) { wnA[ww] = wp[ww*Ww]; wnB[ww] = wp[ww*Ww + 64]; }
            }
            const ull pA0 = pack2(wcA[0],wcA[0]), pA1 = pack2(wcA[1],wcA[1]),
                      pA2 = pack2(wcA[2],wcA[2]), pA3 = pack2(wcA[3],wcA[3]);
            const ull pB0 = pack2(wcB[0],wcB[0]), pB1 = pack2(wcB[1],wcB[1]),
                      pB2 = pack2(wcB[2],wcB[2]), pB3 = pack2(wcB[3],wcB[3]);
#pragma unroll
            for (int k = 0; k < 9; k++) {
                if (k < kcs) {
                    ulonglong2 ra = *reinterpret_cast<const ulonglong2*>(buf + 4352 + (kbs+k)*256 + w*2);
                    ulonglong2 rb = *reinterpret_cast<const ulonglong2*>(buf + 4352 + (kbs+k)*256 + w*2 + 4);
                    fma2(sA[k], ra.x, pA0); fma2(sA[k], ra.y, pA1);
                    fma2(sA[k], rb.x, pA2); fma2(sA[k], rb.y, pA3);
                    fma2(sB[k], ra.x, pB0); fma2(sB[k], ra.y, pB1);
                    fma2(sB[k], rb.x, pB2); fma2(sB[k], rb.y, pB3);
                }
            }
#pragma unroll
            for (int q = 0; q < 4; q++) { wcA[q] = wnA[q]; wcB[q] = wnB[q]; }
        }
#pragma unroll
        for (int k = 0; k < 9; k++) {
            if (k < kcs) {
                float a0, a1; unpack2(sA[k], a0, a1);
                ull* gp = reinterpret_cast<ull*>(buf + (kbs+k)*256 + 2*tc);
                float g0, g1; unpack2(*gp, g0, g1);
                *gp = pack2(g0 + ftanh(a0+sb0a), g1 + ftanh(a1+sb0a));
                unpack2(sB[k], a0, a1);
                gp = reinterpret_cast<ull*>(buf + (kbs+k)*256 + 2*(tc+64));
                unpack2(*gp, g0, g1);
                *gp = pack2(g0 + ftanh(a0+sb0b), g1 + ftanh(a1+sb0b));
            }
        }
        __syncthreads();
    }

    // ---- stage 3 ----
    {
        ull rv = 0ull;
#pragma unroll
        for (int k = 0; k < Kk; k++)
            fma2(rv, *reinterpret_cast<const ull*>(buf + (1+k)*256 + 2*t), ws2[k]);
        *reinterpret_cast<ull*>(sres + 2*t) = rv;
    }
    __syncthreads();

    // ---- stage 4 ----
    {
        ull sa = 0ull, sb = 0ull;
        const float* wb = d_sw1T + t;
#pragma unroll 1
        for (int w = 0; w < Ww; w += 4) {
            const float v0w = wb[(w+0)*Ww];
            const float v1w = wb[(w+1)*Ww];
            const float v2w = wb[(w+2)*Ww];
            const float v3w = wb[(w+3)*Ww];
            ulonglong2 ra = *reinterpret_cast<const ulonglong2*>(sres + w*2);
            ulonglong2 rb = *reinterpret_cast<const ulonglong2*>(sres + w*2 + 4);
            fma2(sa, ra.x, pack2(v0w,v0w)); fma2(sb, ra.y, pack2(v1w,v1w));
            fma2(sa, rb.x, pack2(v2w,v2w)); fma2(sb, rb.y, pack2(v3w,v3w));
        }
        const ull tot = add2(sa, sb);
        float a0, a1; unpack2(tot, a0, a1);
        float v0, v1; unpack2(*reinterpret_cast<const ull*>(buf + 2*t), v0, v1);
        float p0 = (v0 + ftanh(a0+sb1c)) * owc;
        float p1 = (v1 + ftanh(a1+sb1c)) * owc;
#pragma unroll
        for (int o = 16; o > 0; o >>= 1) {
            p0 += __shfl_down_sync(0xffffffffu, p0, o);
            p1 += __shfl_down_sync(0xffffffffu, p1, o);
        }
        if ((t & 31) == 0) { sred[(t>>5)*2] = p0; sred[(t>>5)*2+1] = p1; }
        __syncthreads();
        if (t == 0) {
            d_gdot[(b*Nn+n)*Mm + pair*2 + 0] = sred[0]+sred[2]+sred[4]+sred[6];
            d_gdot[(b*Nn+n)*Mm + pair*2 + 1] = sred[1]+sred[3]+sred[5]+sred[7];
        }
    }
}

// =====================================================================
__global__ void k6_final(const float* __restrict__ boundary,
                         const float* __restrict__ bweights,
                         float* __restrict__ out)
{
    __shared__ float s2[2];
    const int bn = blockIdx.x;
    const int b  = bn >> 5;
    const int t  = threadIdx.x;
    float v = d_gdot[bn*Mm + t] * boundary[b*Mm + t] * bweights[b*Mm + t];
#pragma unroll
    for (int o = 16; o > 0; o >>= 1) v += __shfl_down_sync(0xffffffffu, v, o);
    if ((t & 31) == 0) s2[t >> 5] = v;
    __syncthreads();
    if (t == 0) out[bn] = s2[0] + s2[1];
}

// =====================================================================
extern "C" void kernel_launch(void* const* d_in, const int* in_sizes, int n_in,
                              void* d_out, int out_size)
{
    const float* phase    = (const float*)d_in[0];
    const float* bcoords  = (const float*)d_in[1];
    const float* boundary = (const float*)d_in[2];
    const float* bweights = (const float*)d_in[3];
    const float* posc     = (const float*)d_in[4];
    const float* sigma    = (const float*)d_in[5];
    const float* velc     = (const float*)d_in[6];
    const float* vwt      = (const float*)d_in[7];
    const float* scat     = (const float*)d_in[8];
    const float* sscat    = (const float*)d_in[9];
    const float* aw0 = (const float*)d_in[10];
    const float* ab0 = (const float*)d_in[11];
    const float* aw1 = (const float*)d_in[12];
    const float* ab1 = (const float*)d_in[13];
    const float* aw2 = (const float*)d_in[14];
    const float* ab2 = (const float*)d_in[15];
    const float* tw0 = (const float*)d_in[16];
    const float* tb0 = (const float*)d_in[17];
    const float* tw1 = (const float*)d_in[18];
    const float* tb1 = (const float*)d_in[19];
    const float* tw2 = (const float*)d_in[20];
    const float* tb2 = (const float*)d_in[21];
    const float* sw0 = (const float*)d_in[22];
    const float* sb0 = (const float*)d_in[23];
    const float* sw1 = (const float*)d_in[24];
    const float* sb1 = (const float*)d_in[25];
    const float* ow  = (const float*)d_in[26];
    float* out = (float*)d_out;

    k_prep<<<128, 256>>>(tw1, tw2, sw0, sw1);
    k1_attn<<<Bb*Nn*K1, 128>>>(phase, posc, sigma, velc,
                               aw0, ab0, aw1, ab1, aw2, ab2, tw0, tb0);
    k_bm<<<Bb*Mm, TWd>>>(bcoords, tw0);
    k_h0<<<Bb*Nn*Mm, 128>>>();
    k_g1<<<NTILES, 256>>>(tb1);
    k_g2<<<NTILES, 256>>>(tb2);
    k5_scat<<<Bb*Nn*(Mm/2), 128>>>(scat, sscat, vwt, sb0, sb1, ow);
    k6_final<<<Bb*Nn, 64>>>(boundary, bweights, out);
}

// round 17
// speedup vs baseline: 1.9364x; 1.2439x over previous
#include <cuda_runtime.h>
#include <cuda_fp16.h>
#include <math.h>
#include <cstdint>

#define Bb 4
#define Nn 32
#define Mm 64
#define Kk 16
#define K1 17
#define Pp 128
#define Ww 128
#define TWd 256
#define NROWS (Bb*Nn*Mm*K1)      /* 139264 */
#define NTILES (NROWS/128)       /* 1088 */

typedef unsigned long long ull;

// ---------- f32x2 helpers ----------
__device__ __forceinline__ ull pack2(float a, float b) {
    ull r; asm("mov.b64 %0, {%1, %2};" : "=l"(r) : "f"(a), "f"(b)); return r;
}
__device__ __forceinline__ void unpack2(ull v, float& a, float& b) {
    asm("mov.b64 {%0, %1}, %2;" : "=f"(a), "=f"(b) : "l"(v));
}
__device__ __forceinline__ void fma2(ull& d, ull a, ull b) {
    asm("fma.rn.f32x2 %0, %1, %2, %0;" : "+l"(d) : "l"(a), "l"(b));
}
__device__ __forceinline__ ull add2(ull a, ull b) {
    ull r; asm("add.rn.f32x2 %0, %1, %2;" : "=l"(r) : "l"(a), "l"(b)); return r;
}
__device__ __forceinline__ float ftanh(float x) {
    float e = __expf(2.0f * x);
    return 1.0f - __fdividef(2.0f, e + 1.0f);
}
// fp16 split helpers
__device__ __forceinline__ unsigned short hfh(float x) {
    __half h = __float2half_rn(x);
    return *reinterpret_cast<unsigned short*>(&h);
}
__device__ __forceinline__ unsigned short hfl(float x) {
    __half h = __float2half_rn(x);
    float r = x - __half2float(h);
    __half l = __float2half_rn(r);
    return *reinterpret_cast<unsigned short*>(&l);
}
__device__ __forceinline__ unsigned packh2(float a, float b) {
    return (unsigned)hfh(a) | ((unsigned)hfh(b) << 16);
}
__device__ __forceinline__ unsigned packl2(float a, float b) {
    return (unsigned)hfl(a) | ((unsigned)hfl(b) << 16);
}
__device__ __forceinline__ uint32_t smem_to_u32(const void* p) {
    uint32_t a;
    asm("{ .reg .u64 tmp; cvta.to.shared.u64 tmp, %1; cvt.u32.u64 %0, tmp; }" : "=r"(a) : "l"(p));
    return a;
}
__device__ __forceinline__ void ldm_x4(uint32_t& r0, uint32_t& r1, uint32_t& r2, uint32_t& r3, uint32_t addr) {
    asm volatile("ldmatrix.sync.aligned.m8n8.x4.shared.b16 {%0,%1,%2,%3}, [%4];"
                 : "=r"(r0), "=r"(r1), "=r"(r2), "=r"(r3) : "r"(addr));
}
__device__ __forceinline__ void mma16816(float* c, const uint32_t* a, uint32_t b0, uint32_t b1) {
    asm volatile("mma.sync.aligned.m16n8k16.row.col.f32.f16.f16.f32 "
                 "{%0,%1,%2,%3}, {%4,%5,%6,%7}, {%8,%9}, {%0,%1,%2,%3};"
                 : "+f"(c[0]), "+f"(c[1]), "+f"(c[2]), "+f"(c[3])
                 : "r"(a[0]), "r"(a[1]), "r"(a[2]), "r"(a[3]), "r"(b0), "r"(b1));
}
__device__ __forceinline__ void cp16(uint32_t saddr, const void* gaddr) {
    asm volatile("cp.async.cg.shared.global [%0], [%1], 16;" :: "r"(saddr), "l"(gaddr));
}
#define CP_COMMIT() asm volatile("cp.async.commit_group;" ::: "memory")
#define CP_WAIT(n)  asm volatile("cp.async.wait_group %0;" :: "n"(n) : "memory")

// ------- scratch (device globals; no runtime allocation) -------
__device__ float d_A[Bb*Nn*K1*TWd];
__device__ float d_Bm[Bb*Mm*TWd];
__device__ float d_gdot[Bb*Nn*Mm];
__device__ float d_sw0T[Ww*Ww];             // [w][i]
__device__ float d_sw1T[Ww*Ww];             // [w][i]
__device__ unsigned d_W1hT[256*128];        // [n][kpair] f16x2 (hi)
__device__ unsigned d_W1lT[256*128];        // (lo)
__device__ unsigned d_W2hT[128*128];
__device__ unsigned d_W2lT[128*128];
__device__ unsigned d_H0h[NROWS*128];       // [row][kpair] f16x2 hi
__device__ unsigned d_H1h[NROWS*128];
__device__ float    d_g [NROWS*128];

// =====================================================================
// K_prep: fp16-split transposed weights + sw transposes
// =====================================================================
__global__ void k_prep(const float* __restrict__ tw1, const float* __restrict__ tw2,
                       const float* __restrict__ sw0, const float* __restrict__ sw1)
{
    const int idx = blockIdx.x*256 + threadIdx.x;   // 0..32767
    {
        const int n = idx >> 7, kp = idx & 127;
        const float w0 = tw1[(2*kp)*256 + n];
        const float w1 = tw1[(2*kp+1)*256 + n];
        d_W1hT[n*128 + kp] = packh2(w0, w1);
        d_W1lT[n*128 + kp] = packl2(w0, w1);
    }
    if (idx < 16384) {
        const int n = idx >> 7, kp = idx & 127;
        const float w0 = tw2[(2*kp)*128 + n];
        const float w1 = tw2[(2*kp+1)*128 + n];
        d_W2hT[n*128 + kp] = packh2(w0, w1);
        d_W2lT[n*128 + kp] = packl2(w0, w1);
        const int i = idx >> 7, w = idx & 127;
        d_sw0T[w*Ww + i] = sw0[idx];
        d_sw1T[w*Ww + i] = sw1[idx];
    }
}

// =====================================================================
// K1: attention MLP + softmax + coeff + A-partial.  One block per (b,n,k1).
// =====================================================================
__global__ void __launch_bounds__(128) k1_attn(
    const float* __restrict__ phase, const float* __restrict__ posc,
    const float* __restrict__ sigma, const float* __restrict__ velc,
    const float* __restrict__ aw0, const float* __restrict__ ab0,
    const float* __restrict__ aw1, const float* __restrict__ ab1,
    const float* __restrict__ aw2, const float* __restrict__ ab2,
    const float* __restrict__ tw0, const float* __restrict__ tb0)
{
    __shared__ float s_aw0[6*64];
    __shared__ float s_ab0[64];
    __shared__ float s_aw1[64*64];
    __shared__ float s_ab1[64];
    __shared__ float s_aw2[64];
    __shared__ float red[128];

    const int bx = blockIdx.x;
    const int k1 = bx % K1;
    const int n  = (bx / K1) % Nn;
    const int b  = bx / (K1*Nn);
    const int t  = threadIdx.x;

    for (int i = t; i < 6*64; i += 128) s_aw0[i] = aw0[i];
    if (t < 64) { s_ab0[t] = ab0[t]; s_aw2[t] = aw2[t]; s_ab1[t] = ab1[t]; }
    for (int i = t; i < 64*64; i += 128) s_aw1[i] = aw1[i];
    __syncthreads();

    const float x0 = phase[(b*Nn+n)*4 + 0];
    const float x1 = phase[(b*Nn+n)*4 + 1];
    float va0, va1;
    if (k1 == 0) { va0 = phase[(b*Nn+n)*4 + 2]; va1 = phase[(b*Nn+n)*4 + 3]; }
    else         { va0 = velc[(b*Kk + (k1-1))*2 + 0]; va1 = velc[(b*Kk + (k1-1))*2 + 1]; }
    const float inv = rsqrtf(va0*va0 + va1*va1 + 1e-16f);
    const float ag0 = va0*inv, ag1 = va1*inv;

    const float rx = x0 - posc[(b*Pp + t)*2 + 0];
    const float ry = x1 - posc[(b*Pp + t)*2 + 1];
    const float rd = sqrtf(rx*rx + ry*ry + 1e-16f);
    const float pl = rx*ag0 + ry*ag1;
    const float al = pl / (rd + 1e-8f);

    float h0[64];
#pragma unroll
    for (int j = 0; j < 64; j++) {
        h0[j] = ftanh(s_ab0[j] + x0*s_aw0[0*64+j] + x1*s_aw0[1*64+j]
                              + va0*s_aw0[2*64+j] + va1*s_aw0[3*64+j]
                              + al*s_aw0[4*64+j] + pl*s_aw0[5*64+j]);
    }
    float logit = ab2[0];
#pragma unroll
    for (int g = 0; g < 4; g++) {
        ull acc[8];
#pragma unroll
        for (int p = 0; p < 8; p++) acc[p] = 0ull;
        for (int j = 0; j < 64; j++) {
            const ull hp = pack2(h0[j], h0[j]);
            const float* wrow = &s_aw1[j*64 + g*16];
            ulonglong2 wA = *reinterpret_cast<const ulonglong2*>(wrow + 0);
            ulonglong2 wB = *reinterpret_cast<const ulonglong2*>(wrow + 4);
            ulonglong2 wC = *reinterpret_cast<const ulonglong2*>(wrow + 8);
            ulonglong2 wD = *reinterpret_cast<const ulonglong2*>(wrow + 12);
            fma2(acc[0], hp, wA.x); fma2(acc[1], hp, wA.y);
            fma2(acc[2], hp, wB.x); fma2(acc[3], hp, wB.y);
            fma2(acc[4], hp, wC.x); fma2(acc[5], hp, wC.y);
            fma2(acc[6], hp, wD.x); fma2(acc[7], hp, wD.y);
        }
#pragma unroll
        for (int p = 0; p < 8; p++) {
            const int i = g*16 + p*2;
            float a0, a1; unpack2(acc[p], a0, a1);
            logit += ftanh(a0 + s_ab1[i])   * s_aw2[i]
                   + ftanh(a1 + s_ab1[i+1]) * s_aw2[i+1];
        }
    }

    float lg = (pl > 0.0f) ? logit : -1e30f;
    red[t] = lg; __syncthreads();
    for (int s = 64; s > 0; s >>= 1) { if (t < s) red[t] = fmaxf(red[t], red[t+s]); __syncthreads(); }
    const float mx = red[0]; __syncthreads();
    const float e = __expf(lg - mx);
    red[t] = e; __syncthreads();
    for (int s = 64; s > 0; s >>= 1) { if (t < s) red[t] += red[t+s]; __syncthreads(); }
    const float denom = red[0]; __syncthreads();
    const float aw = e / denom;

    const float sg0 = sigma[(b*Pp+t)*2 + 0];
    const float sg1 = sigma[(b*Pp+t)*2 + 1];
    red[t] = aw*sg0; __syncthreads();
    for (int s = 64; s > 0; s >>= 1) { if (t < s) red[t] += red[t+s]; __syncthreads(); }
    const float sum0 = red[0]; __syncthreads();
    red[t] = aw*sg1; __syncthreads();
    for (int s = 64; s > 0; s >>= 1) { if (t < s) red[t] += red[t+s]; __syncthreads(); }
    const float sum1 = red[0]; __syncthreads();

    const float c0 = __expf(-sum0);
    const float c1 = __expf(-sum1);

    for (int tt = t; tt < TWd; tt += 128) {
        float a = tb0[tt]
                + x0*tw0[0*TWd+tt] + x1*tw0[1*TWd+tt]
                + va0*tw0[2*TWd+tt] + va1*tw0[3*TWd+tt]
                + c0*tw0[8*TWd+tt] + c1*tw0[9*TWd+tt];
        d_A[bx*TWd + tt] = a;
    }
}

// =====================================================================
__global__ void k_bm(const float* __restrict__ bcoords, const float* __restrict__ tw0)
{
    const int bm = blockIdx.x;
    const int t  = threadIdx.x;
    const float xp0 = bcoords[bm*4+0], xp1 = bcoords[bm*4+1];
    const float vp0 = bcoords[bm*4+2], vp1 = bcoords[bm*4+3];
    d_Bm[bm*TWd + t] = xp0*tw0[4*TWd+t] + xp1*tw0[5*TWd+t]
                     + vp0*tw0[6*TWd+t] + vp1*tw0[7*TWd+t];
}

// =====================================================================
// K_h0: H0 = tanh(A + Bm), fp16 hi only.  Block per (b,n,m).
// =====================================================================
__global__ void __launch_bounds__(128) k_h0()
{
    const int bnm = blockIdx.x;            // 0..8191
    const int m   = bnm & 63;
    const int bn  = bnm >> 6;              // b*32+n
    const int t   = threadIdx.x;           // pair index 0..127
    const float* Arow = d_A + bn*K1*TWd;
    const float* Bm   = d_Bm + ((bn >> 5)*Mm + m)*TWd;
    const float bm0 = Bm[2*t], bm1 = Bm[2*t+1];
#pragma unroll
    for (int k = 0; k < K1; k++) {
        const float v0 = ftanh(Arow[k*TWd + 2*t]     + bm0);
        const float v1 = ftanh(Arow[k*TWd + 2*t + 1] + bm1);
        d_H0h[(bnm*K1 + k)*128 + t] = packh2(v0, v1);
    }
}

// =====================================================================
// K_g1: H1 = tanh(H0 @ tw1 + tb1).  fp16 2-term (Ah*Bh + Ah*Bl),
// cp.async double-buffered; 3 stage arrays (A_h, B_h, B_l).
// =====================================================================
__global__ void __launch_bounds__(256, 2) k_g1(const float* __restrict__ tb1)
{
    __shared__ unsigned stage[2][3][128*12];

    const int t   = threadIdx.x;
    const int lid = t & 31, wid = t >> 5;
    const int wm  = wid >> 2, wn = wid & 3;
    const int row0 = blockIdx.x * 128;
    const int lr = lid >> 2, lc = lid & 3;

    const int cr = t >> 1, cj4 = t & 1;
    const uint32_t s_base = smem_to_u32(stage);
    const uint32_t cp_off = (uint32_t)((cr*12 + cj4*4)*4);

    const int arow  = wm*64 + (lid & 7) + ((lid >> 3) & 1)*8;
    const uint32_t a_off = (uint32_t)(arow*48 + ((lid >> 4)*8)*2);
    const int brow  = wn*32 + ((lid >> 4)*8) + (lid & 7);
    const uint32_t b_off = (uint32_t)(brow*48 + (((lid >> 3) & 1)*8)*2);
    const uint32_t ARR = 128u*12u*4u;      // bytes per array
    const uint32_t BUF = 3u*ARR;           // bytes per buffer

    for (int pass = 0; pass < 2; pass++) {
        float acc[4][4][4];
#pragma unroll
        for (int mi = 0; mi < 4; mi++)
#pragma unroll
            for (int ni = 0; ni < 4; ni++)
#pragma unroll
                for (int e = 0; e < 4; e++) acc[mi][ni][e] = 0.0f;

        {
            const int cp = 0*8 + cj4*4;
            cp16(s_base + 0*BUF + 0*ARR + cp_off, &d_H0h[(row0 + cr)*128 + cp]);
            cp16(s_base + 0*BUF + 1*ARR + cp_off, &d_W1hT[(pass*128 + cr)*128 + cp]);
            cp16(s_base + 0*BUF + 2*ARR + cp_off, &d_W1lT[(pass*128 + cr)*128 + cp]);
            CP_COMMIT();
        }

#pragma unroll 1
        for (int kc = 0; kc < 16; kc++) {
            if (kc + 1 < 16) {
                const uint32_t bs = s_base + (uint32_t)((kc+1) & 1)*BUF;
                const int cp = (kc+1)*8 + cj4*4;
                cp16(bs + 0*ARR + cp_off, &d_H0h[(row0 + cr)*128 + cp]);
                cp16(bs + 1*ARR + cp_off, &d_W1hT[(pass*128 + cr)*128 + cp]);
                cp16(bs + 2*ARR + cp_off, &d_W1lT[(pass*128 + cr)*128 + cp]);
                CP_COMMIT();
                CP_WAIT(1);
            } else {
                CP_WAIT(0);
            }
            __syncthreads();

            const uint32_t bs = s_base + (uint32_t)(kc & 1)*BUF;
            uint32_t ah[4][4];
#pragma unroll
            for (int mi = 0; mi < 4; mi++)
                ldm_x4(ah[mi][0], ah[mi][1], ah[mi][2], ah[mi][3],
                       bs + 0*ARR + a_off + (uint32_t)(mi*16*48));
            uint32_t bh[2][4], bl[2][4];
#pragma unroll
            for (int h = 0; h < 2; h++) {
                ldm_x4(bh[h][0], bh[h][1], bh[h][2], bh[h][3],
                       bs + 1*ARR + b_off + (uint32_t)(h*16*48));
                ldm_x4(bl[h][0], bl[h][1], bl[h][2], bl[h][3],
                       bs + 2*ARR + b_off + (uint32_t)(h*16*48));
            }
#pragma unroll
            for (int mi = 0; mi < 4; mi++)
#pragma unroll
                for (int ni = 0; ni < 4; ni++) {
                    const int h = ni >> 1, p = ni & 1;
                    mma16816(acc[mi][ni], ah[mi], bh[h][p*2], bh[h][p*2+1]);
                }
#pragma unroll
            for (int mi = 0; mi < 4; mi++)
#pragma unroll
                for (int ni = 0; ni < 4; ni++) {
                    const int h = ni >> 1, p = ni & 1;
                    mma16816(acc[mi][ni], ah[mi], bl[h][p*2], bl[h][p*2+1]);
                }
            __syncthreads();
        }

        // epilogue: tanh + fp16-hi pack
#pragma unroll
        for (int mi = 0; mi < 4; mi++) {
#pragma unroll
            for (int ni = 0; ni < 4; ni++) {
                const int r0 = row0 + wm*64 + mi*16 + lr;
                const int colg = pass*128 + wn*32 + ni*8 + 2*lc;
                const float bb0 = __ldg(&tb1[colg]);
                const float bb1 = __ldg(&tb1[colg+1]);
                const float t0 = ftanh(acc[mi][ni][0] + bb0);
                const float t1 = ftanh(acc[mi][ni][1] + bb1);
                const float t2 = ftanh(acc[mi][ni][2] + bb0);
                const float t3 = ftanh(acc[mi][ni][3] + bb1);
                const int cp = colg >> 1;
                d_H1h[r0*128 + cp]     = packh2(t0, t1);
                d_H1h[(r0+8)*128 + cp] = packh2(t2, t3);
            }
        }
        __syncthreads();
    }
}

// =====================================================================
// K_g2: g = exp(tanh(H1 @ tw2 + tb2)).  fp16 2-term, same pipeline.
// =====================================================================
__global__ void __launch_bounds__(256, 2) k_g2(const float* __restrict__ tb2)
{
    __shared__ unsigned stage[2][3][128*12];

    const int t   = threadIdx.x;
    const int lid = t & 31, wid = t >> 5;
    const int wm  = wid >> 2, wn = wid & 3;
    const int row0 = blockIdx.x * 128;
    const int lr = lid >> 2, lc = lid & 3;

    const int cr = t >> 1, cj4 = t & 1;
    const uint32_t s_base = smem_to_u32(stage);
    const uint32_t cp_off = (uint32_t)((cr*12 + cj4*4)*4);

    const int arow  = wm*64 + (lid & 7) + ((lid >> 3) & 1)*8;
    const uint32_t a_off = (uint32_t)(arow*48 + ((lid >> 4)*8)*2);
    const int brow  = wn*32 + ((lid >> 4)*8) + (lid & 7);
    const uint32_t b_off = (uint32_t)(brow*48 + (((lid >> 3) & 1)*8)*2);
    const uint32_t ARR = 128u*12u*4u;
    const uint32_t BUF = 3u*ARR;

    float acc[4][4][4];
#pragma unroll
    for (int mi = 0; mi < 4; mi++)
#pragma unroll
        for (int ni = 0; ni < 4; ni++)
#pragma unroll
            for (int e = 0; e < 4; e++) acc[mi][ni][e] = 0.0f;

    {
        const int cp = cj4*4;
        cp16(s_base + 0*BUF + 0*ARR + cp_off, &d_H1h[(row0 + cr)*128 + cp]);
        cp16(s_base + 0*BUF + 1*ARR + cp_off, &d_W2hT[cr*128 + cp]);
        cp16(s_base + 0*BUF + 2*ARR + cp_off, &d_W2lT[cr*128 + cp]);
        CP_COMMIT();
    }

#pragma unroll 1
    for (int kc = 0; kc < 16; kc++) {
        if (kc + 1 < 16) {
            const uint32_t bs = s_base + (uint32_t)((kc+1) & 1)*BUF;
            const int cp = (kc+1)*8 + cj4*4;
            cp16(bs + 0*ARR + cp_off, &d_H1h[(row0 + cr)*128 + cp]);
            cp16(bs + 1*ARR + cp_off, &d_W2hT[cr*128 + cp]);
            cp16(bs + 2*ARR + cp_off, &d_W2lT[cr*128 + cp]);
            CP_COMMIT();
            CP_WAIT(1);
        } else {
            CP_WAIT(0);
        }
        __syncthreads();

        const uint32_t bs = s_base + (uint32_t)(kc & 1)*BUF;
        uint32_t ah[4][4];
#pragma unroll
        for (int mi = 0; mi < 4; mi++)
            ldm_x4(ah[mi][0], ah[mi][1], ah[mi][2], ah[mi][3],
                   bs + 0*ARR + a_off + (uint32_t)(mi*16*48));
        uint32_t bh[2][4], bl[2][4];
#pragma unroll
        for (int h = 0; h < 2; h++) {
            ldm_x4(bh[h][0], bh[h][1], bh[h][2], bh[h][3],
                   bs + 1*ARR + b_off + (uint32_t)(h*16*48));
            ldm_x4(bl[h][0], bl[h][1], bl[h][2], bl[h][3],
                   bs + 2*ARR + b_off + (uint32_t)(h*16*48));
        }
#pragma unroll
        for (int mi = 0; mi < 4; mi++)
#pragma unroll
            for (int ni = 0; ni < 4; ni++) {
                const int h = ni >> 1, p = ni & 1;
                mma16816(acc[mi][ni], ah[mi], bh[h][p*2], bh[h][p*2+1]);
            }
#pragma unroll
        for (int mi = 0; mi < 4; mi++)
#pragma unroll
            for (int ni = 0; ni < 4; ni++) {
                const int h = ni >> 1, p = ni & 1;
                mma16816(acc[mi][ni], ah[mi], bl[h][p*2], bl[h][p*2+1]);
            }
        __syncthreads();
    }

#pragma unroll
    for (int mi = 0; mi < 4; mi++) {
#pragma unroll
        for (int ni = 0; ni < 4; ni++) {
            const int r0 = row0 + wm*64 + mi*16 + lr;
            const int colg = wn*32 + ni*8 + 2*lc;
            const float bb0 = __ldg(&tb2[colg]);
            const float bb1 = __ldg(&tb2[colg+1]);
            float2 v0, v1;
            v0.x = __expf(ftanh(acc[mi][ni][0] + bb0));
            v0.y = __expf(ftanh(acc[mi][ni][1] + bb1));
            v1.x = __expf(ftanh(acc[mi][ni][2] + bb0));
            v1.y = __expf(ftanh(acc[mi][ni][3] + bb1));
            *reinterpret_cast<float2*>(&d_g[r0*128 + colg])     = v0;
            *reinterpret_cast<float2*>(&d_g[(r0+8)*128 + colg]) = v1;
        }
    }
}

// =====================================================================
// K5: scattering chain on g (f32x2 over the m-pair), per (b,n,m-pair).
// =====================================================================
__global__ void __launch_bounds__(128) k5_scat(
    const float* __restrict__ scat, const float* __restrict__ sscat,
    const float* __restrict__ vwt,
    const float* __restrict__ sb0, const float* __restrict__ sb1,
    const float* __restrict__ out_w)
{
    __shared__ float buf[8704];      // g(17x256 pairs) | rr(17x256) at +4352
    __shared__ ull   ws2[272];
    __shared__ float sres[256];
    __shared__ float sred[8];

    const int bx   = blockIdx.x;              // 0..4095
    const int pair = bx & 31;
    const int n    = (bx >> 5) & 31;
    const int b    = bx >> 10;
    const int t    = threadIdx.x;
    const int th   = t >> 6;
    const int tc   = t & 63;
    const int kbs  = th ? 9 : 0;
    const int kcs  = th ? 8 : 9;

    for (int i = t; i < 272; i += 128) {
        const int row = i >> 4, j = i & 15;
        float v = (row == 0) ? (1.0f - scat[(b*Nn+n)*Kk + j])
                             : (1.0f - sscat[b*256 + (row-1)*Kk + j]);
        v *= vwt[b*Kk + j];
        ws2[i] = pack2(v, v);
    }

    const int bnm0 = ((b*Nn + n)*Mm + pair*2);
#pragma unroll
    for (int k = 0; k < K1; k++) {
        const float g0 = d_g[(bnm0*K1 + k)*128 + t];
        const float g1 = d_g[((bnm0+1)*K1 + k)*128 + t];
        *reinterpret_cast<ull*>(buf + k*256 + 2*t) = pack2(g0, g1);
    }
    __syncthreads();

    const float sb0a = sb0[tc], sb0b = sb0[tc+64];
    const float sb1c = sb1[t];
    const float owc  = out_w[t];

    // ---- stage 1: rr[k] = sum_j ws2[k][j]*g[1+j] ----
    {
        ull g2r[Kk];
#pragma unroll
        for (int j = 0; j < Kk; j++)
            g2r[j] = *reinterpret_cast<const ull*>(buf + (1+j)*256 + 2*t);
#pragma unroll
        for (int k = 0; k < K1; k++) {
            ull r = 0ull;
            const ulonglong2* wsp = reinterpret_cast<const ulonglong2*>(ws2 + k*Kk);
#pragma unroll
            for (int jp = 0; jp < 8; jp++) {
                const ulonglong2 wv = wsp[jp];
                fma2(r, g2r[2*jp],   wv.x);
                fma2(r, g2r[2*jp+1], wv.y);
            }
            *reinterpret_cast<ull*>(buf + 4352 + k*256 + 2*t) = r;
        }
        __syncthreads();
    }

    // ---- stage 2: g[k][c] += tanh(sw0T[:,c]@rr[k][:] + sb0[c]); k-split, 2 cols ----
    {
        ull sA[9], sB[9];
#pragma unroll
        for (int k = 0; k < 9; k++) { sA[k] = 0ull; sB[k] = 0ull; }
        const float* wb = d_sw0T + tc;
        float wcA[4], wcB[4], wnA[4], wnB[4];
#pragma unroll
        for (int ww = 0; ww < 4; ww++) { wcA[ww] = wb[ww*Ww]; wcB[ww] = wb[ww*Ww + 64]; }
#pragma unroll 1
        for (int w = 0; w < Ww; w += 4) {
            if (w + 4 < Ww) {
                const float* wp = wb + (w+4)*Ww;
#pragma unroll
                for (int ww = 0; ww < 4; ww++) { wnA[ww] = wp[ww*Ww]; wnB[ww] = wp[ww*Ww + 64]; }
            }
            const ull pA0 = pack2(wcA[0],wcA[0]), pA1 = pack2(wcA[1],wcA[1]),
                      pA2 = pack2(wcA[2],wcA[2]), pA3 = pack2(wcA[3],wcA[3]);
            const ull pB0 = pack2(wcB[0],wcB[0]), pB1 = pack2(wcB[1],wcB[1]),
                      pB2 = pack2(wcB[2],wcB[2]), pB3 = pack2(wcB[3],wcB[3]);
#pragma unroll
            for (int k = 0; k < 9; k++) {
                if (k < kcs) {
                    ulonglong2 ra = *reinterpret_cast<const ulonglong2*>(buf + 4352 + (kbs+k)*256 + w*2);
                    ulonglong2 rb = *reinterpret_cast<const ulonglong2*>(buf + 4352 + (kbs+k)*256 + w*2 + 4);
                    fma2(sA[k], ra.x, pA0); fma2(sA[k], ra.y, pA1);
                    fma2(sA[k], rb.x, pA2); fma2(sA[k], rb.y, pA3);
                    fma2(sB[k], ra.x, pB0); fma2(sB[k], ra.y, pB1);
                    fma2(sB[k], rb.x, pB2); fma2(sB[k], rb.y, pB3);
                }
            }
#pragma unroll
            for (int q = 0; q < 4; q++) { wcA[q] = wnA[q]; wcB[q] = wnB[q]; }
        }
#pragma unroll
        for (int k = 0; k < 9; k++) {
            if (k < kcs) {
                float a0, a1; unpack2(sA[k], a0, a1);
                ull* gp = reinterpret_cast<ull*>(buf + (kbs+k)*256 + 2*tc);
                float g0, g1; unpack2(*gp, g0, g1);
                *gp = pack2(g0 + ftanh(a0+sb0a), g1 + ftanh(a1+sb0a));
                unpack2(sB[k], a0, a1);
                gp = reinterpret_cast<ull*>(buf + (kbs+k)*256 + 2*(tc+64));
                unpack2(*gp, g0, g1);
                *gp = pack2(g0 + ftanh(a0+sb0b), g1 + ftanh(a1+sb0b));
            }
        }
        __syncthreads();
    }

    // ---- stage 3 ----
    {
        ull rv = 0ull;
#pragma unroll
        for (int k = 0; k < Kk; k++)
            fma2(rv, *reinterpret_cast<const ull*>(buf + (1+k)*256 + 2*t), ws2[k]);
        *reinterpret_cast<ull*>(sres + 2*t) = rv;
    }
    __syncthreads();

    // ---- stage 4 ----
    {
        ull sa = 0ull, sb = 0ull;
        const float* wb = d_sw1T + t;
#pragma unroll 1
        for (int w = 0; w < Ww; w += 4) {
            const float v0w = wb[(w+0)*Ww];
            const float v1w = wb[(w+1)*Ww];
            const float v2w = wb[(w+2)*Ww];
            const float v3w = wb[(w+3)*Ww];
            ulonglong2 ra = *reinterpret_cast<const ulonglong2*>(sres + w*2);
            ulonglong2 rb = *reinterpret_cast<const ulonglong2*>(sres + w*2 + 4);
            fma2(sa, ra.x, pack2(v0w,v0w)); fma2(sb, ra.y, pack2(v1w,v1w));
            fma2(sa, rb.x, pack2(v2w,v2w)); fma2(sb, rb.y, pack2(v3w,v3w));
        }
        const ull tot = add2(sa, sb);
        float a0, a1; unpack2(tot, a0, a1);
        float v0, v1; unpack2(*reinterpret_cast<const ull*>(buf + 2*t), v0, v1);
        float p0 = (v0 + ftanh(a0+sb1c)) * owc;
        float p1 = (v1 + ftanh(a1+sb1c)) * owc;
#pragma unroll
        for (int o = 16; o > 0; o >>= 1) {
            p0 += __shfl_down_sync(0xffffffffu, p0, o);
            p1 += __shfl_down_sync(0xffffffffu, p1, o);
        }
        if ((t & 31) == 0) { sred[(t>>5)*2] = p0; sred[(t>>5)*2+1] = p1; }
        __syncthreads();
        if (t == 0) {
            d_gdot[(b*Nn+n)*Mm + pair*2 + 0] = sred[0]+sred[2]+sred[4]+sred[6];
            d_gdot[(b*Nn+n)*Mm + pair*2 + 1] = sred[1]+sred[3]+sred[5]+sred[7];
        }
    }
}

// =====================================================================
__global__ void k6_final(const float* __restrict__ boundary,
                         const float* __restrict__ bweights,
                         float* __restrict__ out)
{
    __shared__ float s2[2];
    const int bn = blockIdx.x;
    const int b  = bn >> 5;
    const int t  = threadIdx.x;
    float v = d_gdot[bn*Mm + t] * boundary[b*Mm + t] * bweights[b*Mm + t];
#pragma unroll
    for (int o = 16; o > 0; o >>= 1) v += __shfl_down_sync(0xffffffffu, v, o);
    if ((t & 31) == 0) s2[t >> 5] = v;
    __syncthreads();
    if (t == 0) out[bn] = s2[0] + s2[1];
}

// =====================================================================
extern "C" void kernel_launch(void* const* d_in, const int* in_sizes, int n_in,
                              void* d_out, int out_size)
{
    const float* phase    = (const float*)d_in[0];
    const float* bcoords  = (const float*)d_in[1];
    const float* boundary = (const float*)d_in[2];
    const float* bweights = (const float*)d_in[3];
    const float* posc     = (const float*)d_in[4];
    const float* sigma    = (const float*)d_in[5];
    const float* velc     = (const float*)d_in[6];
    const float* vwt      = (const float*)d_in[7];
    const float* scat     = (const float*)d_in[8];
    const float* sscat    = (const float*)d_in[9];
    const float* aw0 = (const float*)d_in[10];
    const float* ab0 = (const float*)d_in[11];
    const float* aw1 = (const float*)d_in[12];
    const float* ab1 = (const float*)d_in[13];
    const float* aw2 = (const float*)d_in[14];
    const float* ab2 = (const float*)d_in[15];
    const float* tw0 = (const float*)d_in[16];
    const float* tb0 = (const float*)d_in[17];
    const float* tw1 = (const float*)d_in[18];
    const float* tb1 = (const float*)d_in[19];
    const float* tw2 = (const float*)d_in[20];
    const float* tb2 = (const float*)d_in[21];
    const float* sw0 = (const float*)d_in[22];
    const float* sb0 = (const float*)d_in[23];
    const float* sw1 = (const float*)d_in[24];
    const float* sb1 = (const float*)d_in[25];
    const float* ow  = (const float*)d_in[26];
    float* out = (float*)d_out;

    k_prep<<<128, 256>>>(tw1, tw2, sw0, sw1);
    k1_attn<<<Bb*Nn*K1, 128>>>(phase, posc, sigma, velc,
                               aw0, ab0, aw1, ab1, aw2, ab2, tw0, tb0);
    k_bm<<<Bb*Mm, TWd>>>(bcoords, tw0);
    k_h0<<<Bb*Nn*Mm, 128>>>();
    k_g1<<<NTILES, 256>>>(tb1);
    k_g2<<<NTILES, 256>>>(tb2);
    k5_scat<<<Bb*Nn*(Mm/2), 128>>>(scat, sscat, vwt, sb0, sb1, ow);
    k6_final<<<Bb*Nn, 64>>>(boundary, bweights, out);
}